// round 1
// baseline (speedup 1.0000x reference)
#include <cuda_runtime.h>
#include <math.h>

// Problem constants
#define Bz   4
#define Cc   64
#define Hh   256
#define Ww   256
#define HW   65536
#define HEADS 2
#define CH   32      // channels per head
#define WS   8
#define Dd   64      // WS*WS
#define HID  170
#define C2   340     // 2*HID
#define C3   192     // 3*C
#define PAD  65      // smem row stride for 64-wide rows (conflict-free)

// ------------------------- scratch (device globals; allocation-free) ----------
static __device__ float g_qkv [(size_t)Bz*C3*HW];   // 201 MB
static __device__ float g_qkv2[(size_t)Bz*C3*HW];   // 201 MB
static __device__ float g_x1  [(size_t)Bz*Cc*HW];   //  67 MB
static __device__ float g_mid [(size_t)Bz*C2*HW];   // 357 MB
static __device__ float g_y   [(size_t)Bz*HID*HW];  // 178 MB

// ------------------------- K1/K4: fused LayerNorm + 1x1 conv ------------------
// one thread per pixel; xn kept in registers; weights staged in smem chunks.
template<int COUT, int CHUNK>
__global__ void __launch_bounds__(256) k_ln_conv(const float* __restrict__ xin,
        const float* __restrict__ gw, const float* __restrict__ gb,
        const float* __restrict__ wmat, float* __restrict__ out)
{
    __shared__ float ws[CHUNK * 64];
    const int tid = threadIdx.x;
    const int p   = blockIdx.x * 256 + tid;     // pixel id over B*HW (exact)
    const int b   = p >> 16;
    const int hw  = p & 65535;
    const size_t ibase = (size_t)b * Cc * HW + hw;

    float xv[64];
#pragma unroll
    for (int c = 0; c < 64; c++) xv[c] = xin[ibase + (size_t)c * HW];

    float s = 0.f, s2 = 0.f;
#pragma unroll
    for (int c = 0; c < 64; c++) { s += xv[c]; s2 += xv[c] * xv[c]; }
    const float mu   = s * (1.f / 64.f);
    const float var  = fmaxf(s2 * (1.f / 64.f) - mu * mu, 0.f);
    const float rstd = rsqrtf(var + 1e-5f);
#pragma unroll
    for (int c = 0; c < 64; c++)
        xv[c] = (xv[c] - mu) * rstd * __ldg(&gw[c]) + __ldg(&gb[c]);

    const size_t obase = (size_t)b * COUT * HW + hw;
    for (int ch = 0; ch < COUT; ch += CHUNK) {
        __syncthreads();
        for (int i = tid; i < CHUNK * 64; i += 256) ws[i] = wmat[(size_t)ch * 64 + i];
        __syncthreads();
        for (int o = 0; o < CHUNK; o++) {
            const float4* wr = (const float4*)(ws + o * 64);
            float acc = 0.f;
#pragma unroll
            for (int c4 = 0; c4 < 16; c4++) {
                float4 w4 = wr[c4];
                acc += w4.x * xv[4*c4] + w4.y * xv[4*c4+1]
                     + w4.z * xv[4*c4+2] + w4.w * xv[4*c4+3];
            }
            out[obase + (size_t)(ch + o) * HW] = acc;
        }
    }
}

// ------------------------- depthwise 3x3 helper (cross-correlation, zero pad) -
__device__ __forceinline__ float dw9(const float* __restrict__ ip, int h, int w,
                                     const float* wk)
{
    float acc = 0.f;
#pragma unroll
    for (int kh = 0; kh < 3; kh++) {
        const int hh = h + kh - 1;
        if ((unsigned)hh < 256u) {
            const float* rp = ip + hh * Ww;
#pragma unroll
            for (int kw = 0; kw < 3; kw++) {
                const int ww = w + kw - 1;
                if ((unsigned)ww < 256u) acc += rp[ww] * wk[kh*3 + kw];
            }
        }
    }
    return acc;
}

// ------------------------- K2: depthwise conv 3x3 over CHAN channels ----------
template<int CHAN>
__global__ void __launch_bounds__(256) k_dw(const float* __restrict__ in,
        const float* __restrict__ wt, float* __restrict__ out)
{
    const size_t idx = (size_t)blockIdx.x * 256 + threadIdx.x;  // over B*CHAN*HW
    const int hw = (int)(idx & 65535);
    const int cb = (int)(idx >> 16);        // b*CHAN + ch
    const int ch = cb % CHAN;
    const int h = hw >> 8, w = hw & 255;
    float wk[9];
#pragma unroll
    for (int j = 0; j < 9; j++) wk[j] = __ldg(&wt[ch*9 + j]);
    const float* ip = in + ((size_t)cb << 16);
    out[idx] = dw9(ip, h, w, wk);
}

// ------------------------- K3: fused window attention + proj + residual -------
// one block per 8x8 window; both heads; attention output never leaves smem.
__global__ void __launch_bounds__(256) k_attn(const float* __restrict__ qkv,
        const float* __restrict__ temp, const float* __restrict__ pw,
        const float* __restrict__ pb, const float* __restrict__ xres,
        float* __restrict__ xout)
{
    __shared__ float sq[64 * PAD];   // q, later reused for attention output
    __shared__ float sk[64 * PAD];   // k, later reused for v
    __shared__ float sat[2 * 32 * 32];
    __shared__ float srn[128];       // [0:64) 1/|q_row|, [64:128) 1/|k_row|

    const int tid = threadIdx.x;
    const int win = blockIdx.x;              // B * 32 * 32 windows
    const int b   = win >> 10;
    const int row0 = ((win >> 5) & 31) * WS;
    const int col0 = (win & 31) * WS;

    // ---- load q,k (window gather)
    for (int i = tid; i < 8192; i += 256) {
        const int s = i >> 12;               // 0=q, 1=k
        const int r = i & 4095;
        const int head = r >> 11, ci = (r >> 6) & 31, d = r & 63;
        const int ch = (s * HEADS + head) * CH + ci;
        const size_t g = (size_t)(b * C3 + ch) * HW
                       + (size_t)(row0 + (d >> 3)) * Ww + col0 + (d & 7);
        float* dst = (s == 0) ? sq : sk;
        dst[(head * 32 + ci) * PAD + d] = qkv[g];
    }
    __syncthreads();

    // ---- l2 row norms
    if (tid < 128) {
        const float* rp = ((tid < 64) ? sq : sk) + (tid & 63) * PAD;
        float ss = 0.f;
#pragma unroll
        for (int d = 0; d < 64; d++) ss += rp[d] * rp[d];
        srn[tid] = 1.f / fmaxf(sqrtf(ss), 1e-12f);
    }
    __syncthreads();

    // ---- attn = (q_n . k_n) * temperature
    for (int i = tid; i < 2048; i += 256) {
        const int head = i >> 10, ci = (i >> 5) & 31, e = i & 31;
        const float* qp = sq + (head * 32 + ci) * PAD;
        const float* kp = sk + (head * 32 + e)  * PAD;
        float acc = 0.f;
#pragma unroll
        for (int d = 0; d < 64; d++) acc += qp[d] * kp[d];
        sat[i] = acc * srn[head * 32 + ci] * srn[64 + head * 32 + e]
                     * __ldg(&temp[head]);
    }
    __syncthreads();

    // ---- load v into sk (k no longer needed); softmax rows on first 64 threads
    for (int i = tid; i < 4096; i += 256) {
        const int head = i >> 11, ci = (i >> 6) & 31, d = i & 63;
        const int ch = (2 * HEADS + head) * CH + ci;
        const size_t g = (size_t)(b * C3 + ch) * HW
                       + (size_t)(row0 + (d >> 3)) * Ww + col0 + (d & 7);
        sk[(head * 32 + ci) * PAD + d] = qkv[g];
    }
    if (tid < 64) {
        float* rp = sat + tid * 32;
        float m = -1e30f;
#pragma unroll
        for (int e = 0; e < 32; e++) m = fmaxf(m, rp[e]);
        float ssum = 0.f; float ev[32];
#pragma unroll
        for (int e = 0; e < 32; e++) { ev[e] = __expf(rp[e] - m); ssum += ev[e]; }
        const float inv = 1.f / ssum;
#pragma unroll
        for (int e = 0; e < 32; e++) rp[e] = ev[e] * inv;
    }
    __syncthreads();

    // ---- out = attn @ v  (write into sq; q no longer needed)
    for (int i = tid; i < 4096; i += 256) {
        const int head = i >> 11, ci = (i >> 6) & 31, d = i & 63;
        const float* ap = sat + (head * 32 + ci) * 32;
        const float* vp = sk + head * 32 * PAD + d;
        float acc = 0.f;
#pragma unroll
        for (int e = 0; e < 32; e++) acc += ap[e] * vp[e * PAD];
        sq[(head * 32 + ci) * PAD + d] = acc;
    }
    __syncthreads();

    // ---- proj(1x1) + bias + residual; thread -> (o = tid>>2, 16 pixels)
    {
        const int o  = tid >> 2;
        const int p0 = (tid & 3) * 16;
        float acc[16];
        const float bv = __ldg(&pb[o]);
#pragma unroll
        for (int j = 0; j < 16; j++) acc[j] = bv;
        for (int cc = 0; cc < 64; cc++) {
            const float wv = __ldg(&pw[o * 64 + cc]);
            const float* op = sq + cc * PAD + p0;
#pragma unroll
            for (int j = 0; j < 16; j++) acc[j] += wv * op[j];
        }
        const size_t cbase = (size_t)(b * Cc + o) * HW;
#pragma unroll
        for (int j = 0; j < 16; j++) {
            const int p = p0 + j;
            const size_t g = cbase + (size_t)(row0 + (p >> 3)) * Ww + col0 + (p & 7);
            xout[g] = xres[g] + acc[j];
        }
    }
}

// ------------------------- K5: depthwise 3x3 + GELU gate ----------------------
__global__ void __launch_bounds__(256) k_dwgate(const float* __restrict__ in,
        const float* __restrict__ wt, float* __restrict__ out)
{
    const size_t idx = (size_t)blockIdx.x * 256 + threadIdx.x;  // over B*HID*HW
    const int hw = (int)(idx & 65535);
    const int cb = (int)(idx >> 16);        // b*HID + ch
    const int ch = cb % HID;
    const int b  = cb / HID;
    const int h = hw >> 8, w = hw & 255;

    float w1[9], w2[9];
#pragma unroll
    for (int j = 0; j < 9; j++) w1[j] = __ldg(&wt[ch * 9 + j]);
#pragma unroll
    for (int j = 0; j < 9; j++) w2[j] = __ldg(&wt[(ch + HID) * 9 + j]);

    const float* ip1 = in + (size_t)(b * C2 + ch) * HW;
    const float* ip2 = ip1 + (size_t)HID * HW;
    const float a  = dw9(ip1, h, w, w1);
    const float g2 = dw9(ip2, h, w, w2);
    const float ge = 0.5f * a * (1.0f + erff(a * 0.70710678118654752f));
    out[idx] = ge * g2;
}

// ------------------------- K6: pout 1x1 (170->64) + residual ------------------
__global__ void __launch_bounds__(256) k_pout(const float* __restrict__ y,
        const float* __restrict__ wt, const float* __restrict__ x1,
        float* __restrict__ out)
{
    __shared__ float ws[HID * 64];           // transposed: ws[c*64 + o]
    const int tid = threadIdx.x;
    for (int i = tid; i < HID * 64; i += 256) {
        const int o = i / HID, c = i % HID;  // wt layout [o][c]
        ws[c * 64 + o] = wt[i];
    }
    __syncthreads();

    const int p  = blockIdx.x * 256 + tid;
    const int b  = p >> 16;
    const int hw = p & 65535;

    float acc[64];
#pragma unroll
    for (int o = 0; o < 64; o++) acc[o] = 0.f;

    const float* yp = y + (size_t)b * HID * HW + hw;
    for (int c = 0; c < HID; c++) {
        const float yv = yp[(size_t)c * HW];
        const float4* wr = (const float4*)(ws + c * 64);
#pragma unroll
        for (int o4 = 0; o4 < 16; o4++) {
            float4 w4 = wr[o4];
            acc[4*o4]   += w4.x * yv;
            acc[4*o4+1] += w4.y * yv;
            acc[4*o4+2] += w4.z * yv;
            acc[4*o4+3] += w4.w * yv;
        }
    }

    const size_t gb = (size_t)b * Cc * HW + hw;
#pragma unroll
    for (int o = 0; o < 64; o++) {
        const size_t g = gb + (size_t)o * HW;
        out[g] = x1[g] + acc[o];
    }
}

// ------------------------- launcher ------------------------------------------
extern "C" void kernel_launch(void* const* d_in, const int* in_sizes, int n_in,
                              void* d_out, int out_size)
{
    const float* x     = (const float*)d_in[0];
    const float* ln1w  = (const float*)d_in[1];
    const float* ln1b  = (const float*)d_in[2];
    const float* qkvw  = (const float*)d_in[3];
    const float* qkvdw = (const float*)d_in[4];
    const float* temp  = (const float*)d_in[5];
    const float* projw = (const float*)d_in[6];
    const float* projb = (const float*)d_in[7];
    const float* ln2w  = (const float*)d_in[8];
    const float* ln2b  = (const float*)d_in[9];
    const float* pinw  = (const float*)d_in[10];
    const float* dww   = (const float*)d_in[11];
    const float* poutw = (const float*)d_in[12];
    float* out = (float*)d_out;

    float *qkv, *qkv2, *x1, *mid, *y;
    cudaGetSymbolAddress((void**)&qkv,  g_qkv);
    cudaGetSymbolAddress((void**)&qkv2, g_qkv2);
    cudaGetSymbolAddress((void**)&x1,   g_x1);
    cudaGetSymbolAddress((void**)&mid,  g_mid);
    cudaGetSymbolAddress((void**)&y,    g_y);

    // LN1 + qkv 1x1  (192 outs, two 96-channel weight chunks)
    k_ln_conv<C3, 96><<<(Bz * HW) / 256, 256>>>(x, ln1w, ln1b, qkvw, qkv);
    // depthwise 3x3 on qkv
    k_dw<C3><<<(Bz * C3 * HW) / 256, 256>>>(qkv, qkvdw, qkv2);
    // window attention + proj + residual -> x1
    k_attn<<<Bz * 32 * 32, 256>>>(qkv2, temp, projw, projb, x, x1);
    // LN2 + pin 1x1  (340 outs, four 85-channel weight chunks)
    k_ln_conv<C2, 85><<<(Bz * HW) / 256, 256>>>(x1, ln2w, ln2b, pinw, mid);
    // depthwise 3x3 + GELU gate -> y
    k_dwgate<<<(Bz * HID * HW) / 256, 256>>>(mid, dww, y);
    // pout 1x1 + residual -> out
    k_pout<<<(Bz * HW) / 256, 256>>>(y, poutw, x1, out);
}

// round 2
// speedup vs baseline: 2.0401x; 2.0401x over previous
#include <cuda_runtime.h>
#include <math.h>
#include <stdint.h>

// Problem constants
#define Bz   4
#define Cc   64
#define Hh   256
#define Ww   256
#define HW   65536
#define HEADS 2
#define CH   32
#define WS   8
#define HID  170
#define C2   340
#define C3   192

// ---------------- scratch (device globals) ----------------
static __device__ float g_qkv [(size_t)Bz*C3*HW];
static __device__ float g_qkv2[(size_t)Bz*C3*HW];
static __device__ float g_x1  [(size_t)Bz*Cc*HW];
static __device__ float g_mid [(size_t)Bz*C2*HW];
static __device__ float g_y   [(size_t)Bz*HID*HW];

// ---------------- helpers ----------------
__device__ __forceinline__ uint32_t f2tf32(float x) {
    uint32_t u;
    asm("cvt.rna.tf32.f32 %0, %1;" : "=r"(u) : "f"(x));
    return u;
}
__device__ __forceinline__ float tf32f(float x) { return __uint_as_float(f2tf32(x)); }

__device__ __forceinline__ void mma_tf32(float& c0, float& c1, float& c2, float& c3,
                                         uint32_t a0, uint32_t a1, uint32_t a2, uint32_t a3,
                                         uint32_t b0, uint32_t b1)
{
    asm volatile("mma.sync.aligned.m16n8k8.row.col.f32.tf32.tf32.f32 "
        "{%0,%1,%2,%3}, {%4,%5,%6,%7}, {%8,%9}, {%0,%1,%2,%3};"
        : "+f"(c0), "+f"(c1), "+f"(c2), "+f"(c3)
        : "r"(a0), "r"(a1), "r"(a2), "r"(a3), "r"(b0), "r"(b1));
}

#define SXS 68   // A-tile smem stride (=4 mod 32 -> conflict-free A frags)
#define WSS 72   // B-tile smem stride (=8 mod 32 -> conflict-free B frags)

// ---------------- K1/K4: fused LayerNorm + 1x1 conv via tf32 MMA --------------
// block: 128 threads (4 warps), 64 pixels, K=64, COUT in chunks of 64.
template<int COUT>
__global__ void __launch_bounds__(128) k_ln_mma(const float* __restrict__ xin,
        const float* __restrict__ gw, const float* __restrict__ gb,
        const float* __restrict__ wmat, float* __restrict__ out)
{
    __shared__ float sx[64 * SXS];
    __shared__ float ws[64 * WSS];

    const int tid  = threadIdx.x;
    const int lane = tid & 31;
    const int warp = tid >> 5;
    const int p0   = blockIdx.x * 64;
    const int b    = p0 >> 16;
    const int hw0  = p0 & 65535;

    // ---- LayerNorm prologue: 2 threads per pixel
    {
        const int pl = tid >> 1, half = tid & 1;
        const float* xp = xin + (size_t)(b * 64 + half * 32) * HW + hw0 + pl;
        float xv[32];
        float s = 0.f, s2 = 0.f;
#pragma unroll
        for (int i = 0; i < 32; i++) {
            xv[i] = xp[(size_t)i * HW];
            s += xv[i]; s2 += xv[i] * xv[i];
        }
        s  += __shfl_xor_sync(0xffffffffu, s, 1);
        s2 += __shfl_xor_sync(0xffffffffu, s2, 1);
        const float mu   = s * (1.f / 64.f);
        const float var  = fmaxf(s2 * (1.f / 64.f) - mu * mu, 0.f);
        const float rstd = rsqrtf(var + 1e-5f);
        float* sxp = sx + pl * SXS + half * 32;
#pragma unroll
        for (int i = 0; i < 32; i++) {
            const int c = half * 32 + i;
            sxp[i] = tf32f((xv[i] - mu) * rstd * __ldg(&gw[c]) + __ldg(&gb[c]));
        }
    }
    __syncthreads();

    const int r  = lane >> 2;           // 0..7
    const int c4 = lane & 3;            // 0..3
    const float* ap = sx + (warp * 16 + r) * SXS + c4;
    const float* bp = ws + c4 * WSS + r;

    for (int och = 0; och < COUT; och += 64) {
        if (och) __syncthreads();
        // load W chunk transposed: ws[k][o]
        for (int idx = tid; idx < 64 * 64; idx += 128) {
            const int o = idx >> 6, k = idx & 63;
            float v = (och + o < COUT) ? wmat[(size_t)(och + o) * 64 + k] : 0.f;
            ws[k * WSS + o] = tf32f(v);
        }
        __syncthreads();

        float acc[8][4];
#pragma unroll
        for (int nt = 0; nt < 8; nt++)
#pragma unroll
            for (int j = 0; j < 4; j++) acc[nt][j] = 0.f;

#pragma unroll
        for (int kk = 0; kk < 8; kk++) {
            const int kb = kk * 8;
            const uint32_t a0 = __float_as_uint(ap[kb]);
            const uint32_t a1 = __float_as_uint(ap[8 * SXS + kb]);
            const uint32_t a2 = __float_as_uint(ap[kb + 4]);
            const uint32_t a3 = __float_as_uint(ap[8 * SXS + kb + 4]);
#pragma unroll
            for (int nt = 0; nt < 8; nt++) {
                const uint32_t b0 = __float_as_uint(bp[kb * WSS + nt * 8]);
                const uint32_t b1 = __float_as_uint(bp[(kb + 4) * WSS + nt * 8]);
                mma_tf32(acc[nt][0], acc[nt][1], acc[nt][2], acc[nt][3],
                         a0, a1, a2, a3, b0, b1);
            }
        }

        // store D: c0:(pix r, o), c1:(pix r, o+1), c2:(pix r+8, o), c3:(r+8,o+1)
        const int pixb = hw0 + warp * 16 + r;
#pragma unroll
        for (int nt = 0; nt < 8; nt++) {
            const int o = och + nt * 8 + 2 * c4;
            if (o < COUT) {
                float* op = out + (size_t)(b * COUT + o) * HW + pixb;
                op[0]       = acc[nt][0];
                op[HW]      = acc[nt][1];
                op[8]       = acc[nt][2];
                op[HW + 8]  = acc[nt][3];
            }
        }
    }
}

// ---------------- K6: pout (64 x 170) MMA + residual --------------------------
__global__ void __launch_bounds__(128) k_pout_mma(const float* __restrict__ y,
        const float* __restrict__ wt, const float* __restrict__ x1,
        float* __restrict__ out)
{
    __shared__ float sx[64 * SXS];
    __shared__ float ws[64 * WSS];

    const int tid  = threadIdx.x;
    const int lane = tid & 31;
    const int warp = tid >> 5;
    const int p0   = blockIdx.x * 64;
    const int b    = p0 >> 16;
    const int hw0  = p0 & 65535;

    const int r  = lane >> 2;
    const int c4 = lane & 3;
    const float* ap = sx + (warp * 16 + r) * SXS + c4;
    const float* bp = ws + c4 * WSS + r;

    float acc[8][4];
#pragma unroll
    for (int nt = 0; nt < 8; nt++)
#pragma unroll
        for (int j = 0; j < 4; j++) acc[nt][j] = 0.f;

    for (int kc = 0; kc < HID; kc += 64) {
        const int KC = (HID - kc < 64) ? (HID - kc) : 64;
        if (kc) __syncthreads();
        // activations chunk: sx[pix][k]
        for (int idx = tid; idx < 64 * 64; idx += 128) {
            const int k = idx >> 6, p = idx & 63;
            float v = (k < KC) ? y[(size_t)(b * HID + kc + k) * HW + hw0 + p] : 0.f;
            sx[p * SXS + k] = tf32f(v);
        }
        // weights chunk: ws[k][o], wt layout [o][170]
        for (int idx = tid; idx < 64 * 64; idx += 128) {
            const int o = idx >> 6, k = idx & 63;
            float v = (k < KC) ? wt[(size_t)o * HID + kc + k] : 0.f;
            ws[k * WSS + o] = tf32f(v);
        }
        __syncthreads();

        const int kmax = (KC + 7) >> 3;
        for (int kk = 0; kk < kmax; kk++) {
            const int kb = kk * 8;
            const uint32_t a0 = __float_as_uint(ap[kb]);
            const uint32_t a1 = __float_as_uint(ap[8 * SXS + kb]);
            const uint32_t a2 = __float_as_uint(ap[kb + 4]);
            const uint32_t a3 = __float_as_uint(ap[8 * SXS + kb + 4]);
#pragma unroll
            for (int nt = 0; nt < 8; nt++) {
                const uint32_t b0 = __float_as_uint(bp[kb * WSS + nt * 8]);
                const uint32_t b1 = __float_as_uint(bp[(kb + 4) * WSS + nt * 8]);
                mma_tf32(acc[nt][0], acc[nt][1], acc[nt][2], acc[nt][3],
                         a0, a1, a2, a3, b0, b1);
            }
        }
    }

    const int pixb = hw0 + warp * 16 + r;
#pragma unroll
    for (int nt = 0; nt < 8; nt++) {
        const int o = nt * 8 + 2 * c4;
        const size_t g = (size_t)(b * 64 + o) * HW + pixb;
        out[g]          = x1[g]          + acc[nt][0];
        out[g + HW]     = x1[g + HW]     + acc[nt][1];
        out[g + 8]      = x1[g + 8]      + acc[nt][2];
        out[g + HW + 8] = x1[g + HW + 8] + acc[nt][3];
    }
}

// ---------------- K2/K5: depthwise 3x3 (4-wide vectorized) --------------------
__device__ __forceinline__ void dw4(const float* __restrict__ ip, int h, int w0,
                                    const float* wk, float* acc)
{
#pragma unroll
    for (int kh = 0; kh < 3; kh++) {
        const int hh = h + kh - 1;
        if ((unsigned)hh >= 256u) continue;
        const float* rp = ip + hh * Ww;
        float4 a = *(const float4*)(rp + w0);
        float rl = (w0 > 0)   ? rp[w0 - 1] : 0.f;
        float rr = (w0 < 252) ? rp[w0 + 4] : 0.f;
        float rv[6] = { rl, a.x, a.y, a.z, a.w, rr };
        const float k0 = wk[kh * 3], k1 = wk[kh * 3 + 1], k2 = wk[kh * 3 + 2];
#pragma unroll
        for (int j = 0; j < 4; j++)
            acc[j] += k0 * rv[j] + k1 * rv[j + 1] + k2 * rv[j + 2];
    }
}

template<int CHAN>
__global__ void __launch_bounds__(256) k_dw4(const float* __restrict__ in,
        const float* __restrict__ wt, float* __restrict__ out)
{
    const int idx = blockIdx.x * 256 + threadIdx.x;          // over B*CHAN*HW/4
    const int hwq = idx & 16383;
    const int cb  = idx >> 14;
    const int ch  = cb % CHAN;
    const int h = hwq >> 6, w0 = (hwq & 63) * 4;
    float wk[9];
#pragma unroll
    for (int j = 0; j < 9; j++) wk[j] = __ldg(&wt[ch * 9 + j]);
    const float* ip = in + ((size_t)cb << 16);
    float acc[4] = {0.f, 0.f, 0.f, 0.f};
    dw4(ip, h, w0, wk, acc);
    *(float4*)(out + (size_t)idx * 4) = make_float4(acc[0], acc[1], acc[2], acc[3]);
}

__global__ void __launch_bounds__(256) k_dwgate4(const float* __restrict__ in,
        const float* __restrict__ wt, float* __restrict__ out)
{
    const int idx = blockIdx.x * 256 + threadIdx.x;          // over B*HID*HW/4
    const int hwq = idx & 16383;
    const int cb  = idx >> 14;
    const int ch  = cb % HID;
    const int b   = cb / HID;
    const int h = hwq >> 6, w0 = (hwq & 63) * 4;

    float w1[9], w2[9];
#pragma unroll
    for (int j = 0; j < 9; j++) w1[j] = __ldg(&wt[ch * 9 + j]);
#pragma unroll
    for (int j = 0; j < 9; j++) w2[j] = __ldg(&wt[(ch + HID) * 9 + j]);

    const float* ip1 = in + (size_t)(b * C2 + ch) * HW;
    const float* ip2 = ip1 + (size_t)HID * HW;
    float a1[4] = {0,0,0,0}, a2[4] = {0,0,0,0};
    dw4(ip1, h, w0, w1, a1);
    dw4(ip2, h, w0, w2, a2);
    float o[4];
#pragma unroll
    for (int j = 0; j < 4; j++) {
        const float ge = 0.5f * a1[j] * (1.0f + erff(a1[j] * 0.70710678118654752f));
        o[j] = ge * a2[j];
    }
    *(float4*)(out + (size_t)idx * 4) = make_float4(o[0], o[1], o[2], o[3]);
}

// ---------------- K3: fused window attention + proj + residual ----------------
#define QPAD 68
#define APAD 33
__global__ void __launch_bounds__(256) k_attn(const float* __restrict__ qkv,
        const float* __restrict__ temp, const float* __restrict__ pw,
        const float* __restrict__ pb, const float* __restrict__ xres,
        float* __restrict__ xout)
{
    __shared__ float sq[64 * QPAD];      // q -> attention output
    __shared__ float sk[64 * QPAD];      // k -> v -> proj weights
    __shared__ float sat[64 * APAD];
    __shared__ float srn[128];

    const int tid = threadIdx.x;
    const int win = blockIdx.x;
    const int b    = win >> 10;
    const int row0 = ((win >> 5) & 31) * WS;
    const int col0 = (win & 31) * WS;

    // P1: load q,k
    for (int i = tid; i < 8192; i += 256) {
        const int s = i >> 12;
        const int rr = i & 4095;
        const int head = rr >> 11, ci = (rr >> 6) & 31, d = rr & 63;
        const int ch = (s * HEADS + head) * CH + ci;
        const size_t g = (size_t)(b * C3 + ch) * HW
                       + (size_t)(row0 + (d >> 3)) * Ww + col0 + (d & 7);
        float* dst = (s == 0) ? sq : sk;
        dst[(head * 32 + ci) * QPAD + d] = qkv[g];
    }
    __syncthreads();

    // P2: l2 row norms
    if (tid < 128) {
        const float* rp = ((tid < 64) ? sq : sk) + (tid & 63) * QPAD;
        float ss = 0.f;
#pragma unroll
        for (int j = 0; j < 16; j++) {
            float4 v = *(const float4*)(rp + j * 4);
            ss += v.x * v.x + v.y * v.y + v.z * v.z + v.w * v.w;
        }
        srn[tid] = 1.f / fmaxf(sqrtf(ss), 1e-12f);
    }
    __syncthreads();

    // P3: attn_raw = q . k  (2x4 register tiles, float4 over d)
    {
        const int h   = tid >> 7;
        const int ci0 = ((tid >> 3) & 15) * 2;
        const int e0  = (tid & 7) * 4;
        const float* qp0 = sq + (h * 32 + ci0) * QPAD;
        const float* kp0 = sk + (h * 32 + e0) * QPAD;
        float acc[2][4];
#pragma unroll
        for (int i = 0; i < 2; i++)
#pragma unroll
            for (int j = 0; j < 4; j++) acc[i][j] = 0.f;
#pragma unroll
        for (int d4 = 0; d4 < 16; d4++) {
            float4 q0 = *(const float4*)(qp0 + d4 * 4);
            float4 q1 = *(const float4*)(qp0 + QPAD + d4 * 4);
            float4 kv[4];
#pragma unroll
            for (int j = 0; j < 4; j++)
                kv[j] = *(const float4*)(kp0 + j * QPAD + d4 * 4);
#pragma unroll
            for (int j = 0; j < 4; j++) {
                acc[0][j] += q0.x*kv[j].x + q0.y*kv[j].y + q0.z*kv[j].z + q0.w*kv[j].w;
                acc[1][j] += q1.x*kv[j].x + q1.y*kv[j].y + q1.z*kv[j].z + q1.w*kv[j].w;
            }
        }
        const float tmp = __ldg(&temp[h]);
#pragma unroll
        for (int i = 0; i < 2; i++) {
            const float sqi = srn[h * 32 + ci0 + i] * tmp;
#pragma unroll
            for (int j = 0; j < 4; j++)
                sat[(h * 32 + ci0 + i) * APAD + e0 + j]
                    = acc[i][j] * sqi * srn[64 + h * 32 + e0 + j];
        }
    }
    __syncthreads();

    // P4: load v into sk; softmax on 64 threads
    for (int i = tid; i < 4096; i += 256) {
        const int head = i >> 11, ci = (i >> 6) & 31, d = i & 63;
        const int ch = (2 * HEADS + head) * CH + ci;
        const size_t g = (size_t)(b * C3 + ch) * HW
                       + (size_t)(row0 + (d >> 3)) * Ww + col0 + (d & 7);
        sk[(head * 32 + ci) * QPAD + d] = qkv[g];
    }
    if (tid < 64) {
        float* rp = sat + tid * APAD;
        float m = -1e30f;
#pragma unroll
        for (int e = 0; e < 32; e++) m = fmaxf(m, rp[e]);
        float ssum = 0.f; float ev[32];
#pragma unroll
        for (int e = 0; e < 32; e++) { ev[e] = __expf(rp[e] - m); ssum += ev[e]; }
        const float inv = 1.f / ssum;
#pragma unroll
        for (int e = 0; e < 32; e++) rp[e] = ev[e] * inv;
    }
    __syncthreads();

    // P5: out = attn @ v  -> sq   (2 ci x 8 d register tiles)
    {
        const int h   = tid >> 7;
        const int ci0 = ((tid >> 3) & 15) * 2;
        const int d0  = (tid & 7) * 8;
        const float* ap0 = sat + (h * 32 + ci0) * APAD;
        const float* vp0 = sk + (h * 32) * QPAD + d0;
        float acc[2][8];
#pragma unroll
        for (int i = 0; i < 2; i++)
#pragma unroll
            for (int j = 0; j < 8; j++) acc[i][j] = 0.f;
#pragma unroll
        for (int e = 0; e < 32; e++) {
            const float a0 = ap0[e], a1 = ap0[APAD + e];
            float4 v0 = *(const float4*)(vp0 + e * QPAD);
            float4 v1 = *(const float4*)(vp0 + e * QPAD + 4);
            acc[0][0] += a0*v0.x; acc[0][1] += a0*v0.y; acc[0][2] += a0*v0.z; acc[0][3] += a0*v0.w;
            acc[0][4] += a0*v1.x; acc[0][5] += a0*v1.y; acc[0][6] += a0*v1.z; acc[0][7] += a0*v1.w;
            acc[1][0] += a1*v0.x; acc[1][1] += a1*v0.y; acc[1][2] += a1*v0.z; acc[1][3] += a1*v0.w;
            acc[1][4] += a1*v1.x; acc[1][5] += a1*v1.y; acc[1][6] += a1*v1.z; acc[1][7] += a1*v1.w;
        }
#pragma unroll
        for (int i = 0; i < 2; i++) {
            float* op = sq + (h * 32 + ci0 + i) * QPAD + d0;
            *(float4*)op       = make_float4(acc[i][0], acc[i][1], acc[i][2], acc[i][3]);
            *(float4*)(op + 4) = make_float4(acc[i][4], acc[i][5], acc[i][6], acc[i][7]);
        }
    }
    __syncthreads();

    // P6: load proj weights transposed into sk region: wsp[k][o], stride QPAD
    {
        float* wsp = sk;
        for (int idx = tid; idx < 64 * 64; idx += 256) {
            const int o = idx >> 6, k = idx & 63;
            wsp[k * QPAD + o] = pw[idx];        // pw[o*64+k]
        }
    }
    __syncthreads();

    // P7: proj + bias + residual.  8 outs x 2 pixels per thread.
    {
        const float* wsp = sk;
        const int o0 = (tid >> 5) * 8;
        const int p0 = (tid & 31) * 2;
        float acc[8][2];
#pragma unroll
        for (int i = 0; i < 8; i++) {
            const float bv = __ldg(&pb[o0 + i]);
            acc[i][0] = bv; acc[i][1] = bv;
        }
        const float* xp = sq + p0;
#pragma unroll
        for (int k = 0; k < 64; k++) {
            float4 wa = *(const float4*)(wsp + k * QPAD + o0);
            float4 wb = *(const float4*)(wsp + k * QPAD + o0 + 4);
            const float x0 = xp[k * QPAD], x1v = xp[k * QPAD + 1];
            acc[0][0] += wa.x*x0; acc[0][1] += wa.x*x1v;
            acc[1][0] += wa.y*x0; acc[1][1] += wa.y*x1v;
            acc[2][0] += wa.z*x0; acc[2][1] += wa.z*x1v;
            acc[3][0] += wa.w*x0; acc[3][1] += wa.w*x1v;
            acc[4][0] += wb.x*x0; acc[4][1] += wb.x*x1v;
            acc[5][0] += wb.y*x0; acc[5][1] += wb.y*x1v;
            acc[6][0] += wb.z*x0; acc[6][1] += wb.z*x1v;
            acc[7][0] += wb.w*x0; acc[7][1] += wb.w*x1v;
        }
        const size_t pixg = (size_t)(row0 + (p0 >> 3)) * Ww + col0 + (p0 & 7);
#pragma unroll
        for (int i = 0; i < 8; i++) {
            const size_t g = (size_t)(b * Cc + o0 + i) * HW + pixg;
            float2 xr = *(const float2*)(xres + g);
            float2 ov = make_float2(xr.x + acc[i][0], xr.y + acc[i][1]);
            *(float2*)(xout + g) = ov;
        }
    }
}

// ---------------- launcher ----------------------------------------------------
extern "C" void kernel_launch(void* const* d_in, const int* in_sizes, int n_in,
                              void* d_out, int out_size)
{
    const float* x     = (const float*)d_in[0];
    const float* ln1w  = (const float*)d_in[1];
    const float* ln1b  = (const float*)d_in[2];
    const float* qkvw  = (const float*)d_in[3];
    const float* qkvdw = (const float*)d_in[4];
    const float* temp  = (const float*)d_in[5];
    const float* projw = (const float*)d_in[6];
    const float* projb = (const float*)d_in[7];
    const float* ln2w  = (const float*)d_in[8];
    const float* ln2b  = (const float*)d_in[9];
    const float* pinw  = (const float*)d_in[10];
    const float* dww   = (const float*)d_in[11];
    const float* poutw = (const float*)d_in[12];
    float* out = (float*)d_out;

    float *qkv, *qkv2, *x1, *mid, *y;
    cudaGetSymbolAddress((void**)&qkv,  g_qkv);
    cudaGetSymbolAddress((void**)&qkv2, g_qkv2);
    cudaGetSymbolAddress((void**)&x1,   g_x1);
    cudaGetSymbolAddress((void**)&mid,  g_mid);
    cudaGetSymbolAddress((void**)&y,    g_y);

    // LN1 + qkv 1x1 (tf32 MMA)
    k_ln_mma<C3><<<(Bz * HW) / 64, 128>>>(x, ln1w, ln1b, qkvw, qkv);
    // depthwise 3x3 on qkv (4-wide)
    k_dw4<C3><<<(Bz * C3 * HW / 4) / 256, 256>>>(qkv, qkvdw, qkv2);
    // window attention + proj + residual -> x1
    k_attn<<<Bz * 32 * 32, 256>>>(qkv2, temp, projw, projb, x, x1);
    // LN2 + pin 1x1 (tf32 MMA)
    k_ln_mma<C2><<<(Bz * HW) / 64, 128>>>(x1, ln2w, ln2b, pinw, mid);
    // depthwise 3x3 + GELU gate (4-wide)
    k_dwgate4<<<(Bz * HID * HW / 4) / 256, 256>>>(mid, dww, y);
    // pout 1x1 (tf32 MMA) + residual -> out
    k_pout_mma<<<(Bz * HW) / 64, 128>>>(y, poutw, x1, out);
}

// round 3
// speedup vs baseline: 2.4091x; 1.1809x over previous
#include <cuda_runtime.h>
#include <math.h>
#include <stdint.h>

// Problem constants
#define Bz   4
#define Cc   64
#define Hh   256
#define Ww   256
#define HW   65536
#define HEADS 2
#define CH   32
#define WS   8
#define HID  170
#define C2   340
#define C3   192

// ---------------- scratch (device globals) ----------------
static __device__ float g_qkv [(size_t)Bz*C3*HW];
static __device__ float g_qkv2[(size_t)Bz*C3*HW];
static __device__ float g_x1  [(size_t)Bz*Cc*HW];
static __device__ float g_mid [(size_t)Bz*C2*HW];
static __device__ float g_y   [(size_t)Bz*HID*HW];
// pre-transposed tf32 weights: [k][o]
static __device__ float g_wq  [64 * 192];
static __device__ float g_wp  [64 * 384];
static __device__ float g_wo  [192 * 64];

// ---------------- helpers ----------------
__device__ __forceinline__ uint32_t f2tf32(float x) {
    uint32_t u;
    asm("cvt.rna.tf32.f32 %0, %1;" : "=r"(u) : "f"(x));
    return u;
}
__device__ __forceinline__ float tf32f(float x) { return __uint_as_float(f2tf32(x)); }

__device__ __forceinline__ void mma_tf32(float& c0, float& c1, float& c2, float& c3,
                                         uint32_t a0, uint32_t a1, uint32_t a2, uint32_t a3,
                                         uint32_t b0, uint32_t b1)
{
    asm volatile("mma.sync.aligned.m16n8k8.row.col.f32.tf32.tf32.f32 "
        "{%0,%1,%2,%3}, {%4,%5,%6,%7}, {%8,%9}, {%0,%1,%2,%3};"
        : "+f"(c0), "+f"(c1), "+f"(c2), "+f"(c3)
        : "r"(a0), "r"(a1), "r"(a2), "r"(a3), "r"(b0), "r"(b1));
}

#define SXS 68   // A-tile stride (=4 mod 32 -> conflict-free A frag loads)
#define WSS 72   // B stride for 64-wide chunks (=8 mod 32)
#define WSS32 40 // B stride for 32-wide chunks (=8 mod 32)

// ---------------- K0: weight prep (transpose + tf32 convert) ------------------
__global__ void __launch_bounds__(256) k_prep(const float* __restrict__ qkvw,
        const float* __restrict__ pinw, const float* __restrict__ poutw,
        float* __restrict__ wq, float* __restrict__ wp, float* __restrict__ wo)
{
    const int t = blockIdx.x * 256 + threadIdx.x;
    if (t < 64 * 192) {                       // wq[k][o] = qkvw[o][k]
        const int k = t / 192, o = t % 192;
        wq[t] = tf32f(qkvw[o * 64 + k]);
    }
    if (t < 64 * 384) {                       // wp[k][o] = pinw[o][k], o<340
        const int k = t / 384, o = t % 384;
        wp[t] = (o < C2) ? tf32f(pinw[o * 64 + k]) : 0.f;
    }
    if (t < 192 * 64) {                       // wo[k][o] = poutw[o][k], k<170
        const int k = t / 64, o = t % 64;
        wo[t] = (k < HID) ? tf32f(poutw[o * HID + k]) : 0.f;
    }
}

// ---------------- K1/K4: fused LayerNorm + 1x1 conv, tf32 MMA v2 --------------
// 256 threads / 128 pixels. A-frags cached in regs across all output chunks.
// Weight chunks of 32 outs, staged conflict-free from pre-transposed wT.
template<int COUT, int CPAD>
__global__ void __launch_bounds__(256) k_ln_mma2(const float* __restrict__ xin,
        const float* __restrict__ gw, const float* __restrict__ gb,
        const float* __restrict__ wT, float* __restrict__ out)
{
    __shared__ float sx[128 * SXS];          // 34.0 KB
    __shared__ float ws[64 * WSS32];         // 10.0 KB

    const int tid  = threadIdx.x;
    const int lane = tid & 31;
    const int warp = tid >> 5;
    const int p0   = blockIdx.x * 128;
    const int b    = p0 >> 16;
    const int hw0  = p0 & 65535;

    // ---- LayerNorm: 2 threads per pixel
    {
        const int pl = tid >> 1, half = tid & 1;
        const float* xp = xin + (size_t)(b * 64 + half * 32) * HW + hw0 + pl;
        float xv[32];
        float s = 0.f, s2 = 0.f;
#pragma unroll
        for (int i = 0; i < 32; i++) {
            xv[i] = xp[(size_t)i * HW];
            s += xv[i]; s2 += xv[i] * xv[i];
        }
        s  += __shfl_xor_sync(0xffffffffu, s, 1);
        s2 += __shfl_xor_sync(0xffffffffu, s2, 1);
        const float mu   = s * (1.f / 64.f);
        const float var  = fmaxf(s2 * (1.f / 64.f) - mu * mu, 0.f);
        const float rstd = rsqrtf(var + 1e-5f);
        float* sxp = sx + pl * SXS + half * 32;
#pragma unroll
        for (int i = 0; i < 32; i++) {
            const int c = half * 32 + i;
            sxp[i] = tf32f((xv[i] - mu) * rstd * __ldg(&gw[c]) + __ldg(&gb[c]));
        }
    }
    __syncthreads();

    const int r  = lane >> 2;
    const int c4 = lane & 3;
    const float* ap = sx + (warp * 16 + r) * SXS + c4;
    const float* bp = ws + c4 * WSS32 + r;

    // ---- cache A fragments in registers (reused for every output chunk)
    uint32_t areg[8][4];
#pragma unroll
    for (int kk = 0; kk < 8; kk++) {
        const int kb = kk * 8;
        areg[kk][0] = __float_as_uint(ap[kb]);
        areg[kk][1] = __float_as_uint(ap[8 * SXS + kb]);
        areg[kk][2] = __float_as_uint(ap[kb + 4]);
        areg[kk][3] = __float_as_uint(ap[kb + 4 + 8 * SXS]);
    }

    const int pixb = hw0 + warp * 16 + r;
    const int NCH  = (COUT + 31) / 32;
    for (int chunk = 0; chunk < NCH; chunk++) {
        const int och = chunk * 32;
        __syncthreads();
        // stage 64x32 weight tile: conflict-free (o consecutive within warp)
        for (int idx = tid; idx < 64 * 32; idx += 256) {
            const int k = idx >> 5, o = idx & 31;
            ws[k * WSS32 + o] = wT[k * CPAD + och + o];
        }
        __syncthreads();

        float acc[4][4];
#pragma unroll
        for (int nt = 0; nt < 4; nt++)
#pragma unroll
            for (int j = 0; j < 4; j++) acc[nt][j] = 0.f;

#pragma unroll
        for (int kk = 0; kk < 8; kk++) {
            const int kb = kk * 8;
#pragma unroll
            for (int nt = 0; nt < 4; nt++) {
                const uint32_t b0 = __float_as_uint(bp[kb * WSS32 + nt * 8]);
                const uint32_t b1 = __float_as_uint(bp[(kb + 4) * WSS32 + nt * 8]);
                mma_tf32(acc[nt][0], acc[nt][1], acc[nt][2], acc[nt][3],
                         areg[kk][0], areg[kk][1], areg[kk][2], areg[kk][3], b0, b1);
            }
        }

#pragma unroll
        for (int nt = 0; nt < 4; nt++) {
            const int o = och + nt * 8 + 2 * c4;
            if ((COUT & 31) == 0 || o < COUT) {
                float* op = out + (size_t)(b * COUT + o) * HW + pixb;
                op[0]      = acc[nt][0];
                op[HW]     = acc[nt][1];
                op[8]      = acc[nt][2];
                op[HW + 8] = acc[nt][3];
            }
        }
    }
}

// ---------------- K6: pout (64 x 170) MMA + residual, v2 ----------------------
__global__ void __launch_bounds__(128) k_pout2(const float* __restrict__ y,
        const float* __restrict__ wT, const float* __restrict__ x1,
        float* __restrict__ out)
{
    __shared__ float sx[64 * SXS];
    __shared__ float ws[64 * WSS];

    const int tid  = threadIdx.x;
    const int lane = tid & 31;
    const int warp = tid >> 5;
    const int p0   = blockIdx.x * 64;
    const int b    = p0 >> 16;
    const int hw0  = p0 & 65535;

    const int r  = lane >> 2;
    const int c4 = lane & 3;
    const float* ap = sx + (warp * 16 + r) * SXS + c4;
    const float* bp = ws + c4 * WSS + r;

    float acc[8][4];
#pragma unroll
    for (int nt = 0; nt < 8; nt++)
#pragma unroll
        for (int j = 0; j < 4; j++) acc[nt][j] = 0.f;

    for (int kc = 0; kc < 192; kc += 64) {
        __syncthreads();
        // stage y chunk [px][k]: coalesced LDG, 4-way STS (accepted)
        {
            const int px = tid & 63, kh = tid >> 6;
            float* sxp = sx + px * SXS + kh * 32;
            const float* yp = y + (size_t)(b * HID + kc + kh * 32) * HW + hw0 + px;
#pragma unroll
            for (int j = 0; j < 32; j++) {
                const int gk = kc + kh * 32 + j;
                sxp[j] = (gk < HID) ? tf32f(yp[(size_t)j * HW]) : 0.f;
            }
        }
        // stage weights conflict-free from pre-transposed wo
        for (int idx = tid; idx < 64 * 64; idx += 128) {
            const int k = idx >> 6, o = idx & 63;
            ws[k * WSS + o] = wT[(kc + k) * 64 + o];
        }
        __syncthreads();

#pragma unroll
        for (int kk = 0; kk < 8; kk++) {
            const int kb = kk * 8;
            const uint32_t a0 = __float_as_uint(ap[kb]);
            const uint32_t a1 = __float_as_uint(ap[8 * SXS + kb]);
            const uint32_t a2 = __float_as_uint(ap[kb + 4]);
            const uint32_t a3 = __float_as_uint(ap[kb + 4 + 8 * SXS]);
#pragma unroll
            for (int nt = 0; nt < 8; nt++) {
                const uint32_t b0 = __float_as_uint(bp[kb * WSS + nt * 8]);
                const uint32_t b1 = __float_as_uint(bp[(kb + 4) * WSS + nt * 8]);
                mma_tf32(acc[nt][0], acc[nt][1], acc[nt][2], acc[nt][3],
                         a0, a1, a2, a3, b0, b1);
            }
        }
    }

    const int pixb = hw0 + warp * 16 + r;
#pragma unroll
    for (int nt = 0; nt < 8; nt++) {
        const int o = nt * 8 + 2 * c4;
        const size_t g = (size_t)(b * 64 + o) * HW + pixb;
        out[g]          = x1[g]          + acc[nt][0];
        out[g + HW]     = x1[g + HW]     + acc[nt][1];
        out[g + 8]      = x1[g + 8]      + acc[nt][2];
        out[g + HW + 8] = x1[g + HW + 8] + acc[nt][3];
    }
}

// ---------------- K2/K5: depthwise 3x3 (4-wide vectorized) --------------------
__device__ __forceinline__ void dw4(const float* __restrict__ ip, int h, int w0,
                                    const float* wk, float* acc)
{
#pragma unroll
    for (int kh = 0; kh < 3; kh++) {
        const int hh = h + kh - 1;
        if ((unsigned)hh >= 256u) continue;
        const float* rp = ip + hh * Ww;
        float4 a = *(const float4*)(rp + w0);
        float rl = (w0 > 0)   ? rp[w0 - 1] : 0.f;
        float rr = (w0 < 252) ? rp[w0 + 4] : 0.f;
        float rv[6] = { rl, a.x, a.y, a.z, a.w, rr };
        const float k0 = wk[kh * 3], k1 = wk[kh * 3 + 1], k2 = wk[kh * 3 + 2];
#pragma unroll
        for (int j = 0; j < 4; j++)
            acc[j] += k0 * rv[j] + k1 * rv[j + 1] + k2 * rv[j + 2];
    }
}

template<int CHAN>
__global__ void __launch_bounds__(256) k_dw4(const float* __restrict__ in,
        const float* __restrict__ wt, float* __restrict__ out)
{
    const int idx = blockIdx.x * 256 + threadIdx.x;
    const int hwq = idx & 16383;
    const int cb  = idx >> 14;
    const int ch  = cb % CHAN;
    const int h = hwq >> 6, w0 = (hwq & 63) * 4;
    float wk[9];
#pragma unroll
    for (int j = 0; j < 9; j++) wk[j] = __ldg(&wt[ch * 9 + j]);
    const float* ip = in + ((size_t)cb << 16);
    float acc[4] = {0.f, 0.f, 0.f, 0.f};
    dw4(ip, h, w0, wk, acc);
    *(float4*)(out + (size_t)idx * 4) = make_float4(acc[0], acc[1], acc[2], acc[3]);
}

__global__ void __launch_bounds__(256) k_dwgate4(const float* __restrict__ in,
        const float* __restrict__ wt, float* __restrict__ out)
{
    const int idx = blockIdx.x * 256 + threadIdx.x;
    const int hwq = idx & 16383;
    const int cb  = idx >> 14;
    const int ch  = cb % HID;
    const int b   = cb / HID;
    const int h = hwq >> 6, w0 = (hwq & 63) * 4;

    float w1[9], w2[9];
#pragma unroll
    for (int j = 0; j < 9; j++) w1[j] = __ldg(&wt[ch * 9 + j]);
#pragma unroll
    for (int j = 0; j < 9; j++) w2[j] = __ldg(&wt[(ch + HID) * 9 + j]);

    const float* ip1 = in + (size_t)(b * C2 + ch) * HW;
    const float* ip2 = ip1 + (size_t)HID * HW;
    float a1[4] = {0,0,0,0}, a2[4] = {0,0,0,0};
    dw4(ip1, h, w0, w1, a1);
    dw4(ip2, h, w0, w2, a2);
    float o[4];
#pragma unroll
    for (int j = 0; j < 4; j++) {
        const float ge = 0.5f * a1[j] * (1.0f + erff(a1[j] * 0.70710678118654752f));
        o[j] = ge * a2[j];
    }
    *(float4*)(out + (size_t)idx * 4) = make_float4(o[0], o[1], o[2], o[3]);
}

// ---------------- K3: fused window attention + proj + residual ----------------
#define QPAD 68
#define APAD 33
__global__ void __launch_bounds__(256) k_attn(const float* __restrict__ qkv,
        const float* __restrict__ temp, const float* __restrict__ pw,
        const float* __restrict__ pb, const float* __restrict__ xres,
        float* __restrict__ xout)
{
    __shared__ float sq[64 * QPAD];
    __shared__ float sk[64 * QPAD];
    __shared__ float sat[64 * APAD];
    __shared__ float srn[128];

    const int tid = threadIdx.x;
    const int win = blockIdx.x;
    const int b    = win >> 10;
    const int row0 = ((win >> 5) & 31) * WS;
    const int col0 = (win & 31) * WS;

    for (int i = tid; i < 8192; i += 256) {
        const int s = i >> 12;
        const int rr = i & 4095;
        const int head = rr >> 11, ci = (rr >> 6) & 31, d = rr & 63;
        const int ch = (s * HEADS + head) * CH + ci;
        const size_t g = (size_t)(b * C3 + ch) * HW
                       + (size_t)(row0 + (d >> 3)) * Ww + col0 + (d & 7);
        float* dst = (s == 0) ? sq : sk;
        dst[(head * 32 + ci) * QPAD + d] = qkv[g];
    }
    __syncthreads();

    if (tid < 128) {
        const float* rp = ((tid < 64) ? sq : sk) + (tid & 63) * QPAD;
        float ss = 0.f;
#pragma unroll
        for (int j = 0; j < 16; j++) {
            float4 v = *(const float4*)(rp + j * 4);
            ss += v.x * v.x + v.y * v.y + v.z * v.z + v.w * v.w;
        }
        srn[tid] = 1.f / fmaxf(sqrtf(ss), 1e-12f);
    }
    __syncthreads();

    {
        const int h   = tid >> 7;
        const int ci0 = ((tid >> 3) & 15) * 2;
        const int e0  = (tid & 7) * 4;
        const float* qp0 = sq + (h * 32 + ci0) * QPAD;
        const float* kp0 = sk + (h * 32 + e0) * QPAD;
        float acc[2][4];
#pragma unroll
        for (int i = 0; i < 2; i++)
#pragma unroll
            for (int j = 0; j < 4; j++) acc[i][j] = 0.f;
#pragma unroll
        for (int d4 = 0; d4 < 16; d4++) {
            float4 q0 = *(const float4*)(qp0 + d4 * 4);
            float4 q1 = *(const float4*)(qp0 + QPAD + d4 * 4);
            float4 kv[4];
#pragma unroll
            for (int j = 0; j < 4; j++)
                kv[j] = *(const float4*)(kp0 + j * QPAD + d4 * 4);
#pragma unroll
            for (int j = 0; j < 4; j++) {
                acc[0][j] += q0.x*kv[j].x + q0.y*kv[j].y + q0.z*kv[j].z + q0.w*kv[j].w;
                acc[1][j] += q1.x*kv[j].x + q1.y*kv[j].y + q1.z*kv[j].z + q1.w*kv[j].w;
            }
        }
        const float tmp = __ldg(&temp[h]);
#pragma unroll
        for (int i = 0; i < 2; i++) {
            const float sqi = srn[h * 32 + ci0 + i] * tmp;
#pragma unroll
            for (int j = 0; j < 4; j++)
                sat[(h * 32 + ci0 + i) * APAD + e0 + j]
                    = acc[i][j] * sqi * srn[64 + h * 32 + e0 + j];
        }
    }
    __syncthreads();

    for (int i = tid; i < 4096; i += 256) {
        const int head = i >> 11, ci = (i >> 6) & 31, d = i & 63;
        const int ch = (2 * HEADS + head) * CH + ci;
        const size_t g = (size_t)(b * C3 + ch) * HW
                       + (size_t)(row0 + (d >> 3)) * Ww + col0 + (d & 7);
        sk[(head * 32 + ci) * QPAD + d] = qkv[g];
    }
    if (tid < 64) {
        float* rp = sat + tid * APAD;
        float m = -1e30f;
#pragma unroll
        for (int e = 0; e < 32; e++) m = fmaxf(m, rp[e]);
        float ssum = 0.f; float ev[32];
#pragma unroll
        for (int e = 0; e < 32; e++) { ev[e] = __expf(rp[e] - m); ssum += ev[e]; }
        const float inv = 1.f / ssum;
#pragma unroll
        for (int e = 0; e < 32; e++) rp[e] = ev[e] * inv;
    }
    __syncthreads();

    {
        const int h   = tid >> 7;
        const int ci0 = ((tid >> 3) & 15) * 2;
        const int d0  = (tid & 7) * 8;
        const float* ap0 = sat + (h * 32 + ci0) * APAD;
        const float* vp0 = sk + (h * 32) * QPAD + d0;
        float acc[2][8];
#pragma unroll
        for (int i = 0; i < 2; i++)
#pragma unroll
            for (int j = 0; j < 8; j++) acc[i][j] = 0.f;
#pragma unroll
        for (int e = 0; e < 32; e++) {
            const float a0 = ap0[e], a1 = ap0[APAD + e];
            float4 v0 = *(const float4*)(vp0 + e * QPAD);
            float4 v1 = *(const float4*)(vp0 + e * QPAD + 4);
            acc[0][0] += a0*v0.x; acc[0][1] += a0*v0.y; acc[0][2] += a0*v0.z; acc[0][3] += a0*v0.w;
            acc[0][4] += a0*v1.x; acc[0][5] += a0*v1.y; acc[0][6] += a0*v1.z; acc[0][7] += a0*v1.w;
            acc[1][0] += a1*v0.x; acc[1][1] += a1*v0.y; acc[1][2] += a1*v0.z; acc[1][3] += a1*v0.w;
            acc[1][4] += a1*v1.x; acc[1][5] += a1*v1.y; acc[1][6] += a1*v1.z; acc[1][7] += a1*v1.w;
        }
#pragma unroll
        for (int i = 0; i < 2; i++) {
            float* op = sq + (h * 32 + ci0 + i) * QPAD + d0;
            *(float4*)op       = make_float4(acc[i][0], acc[i][1], acc[i][2], acc[i][3]);
            *(float4*)(op + 4) = make_float4(acc[i][4], acc[i][5], acc[i][6], acc[i][7]);
        }
    }
    __syncthreads();

    {
        float* wsp = sk;
        for (int idx = tid; idx < 64 * 64; idx += 256) {
            const int o = idx >> 6, k = idx & 63;
            wsp[k * QPAD + o] = pw[idx];
        }
    }
    __syncthreads();

    {
        const float* wsp = sk;
        const int o0 = (tid >> 5) * 8;
        const int p0 = (tid & 31) * 2;
        float acc[8][2];
#pragma unroll
        for (int i = 0; i < 8; i++) {
            const float bv = __ldg(&pb[o0 + i]);
            acc[i][0] = bv; acc[i][1] = bv;
        }
        const float* xp = sq + p0;
#pragma unroll
        for (int k = 0; k < 64; k++) {
            float4 wa = *(const float4*)(wsp + k * QPAD + o0);
            float4 wb = *(const float4*)(wsp + k * QPAD + o0 + 4);
            const float x0 = xp[k * QPAD], x1v = xp[k * QPAD + 1];
            acc[0][0] += wa.x*x0; acc[0][1] += wa.x*x1v;
            acc[1][0] += wa.y*x0; acc[1][1] += wa.y*x1v;
            acc[2][0] += wa.z*x0; acc[2][1] += wa.z*x1v;
            acc[3][0] += wa.w*x0; acc[3][1] += wa.w*x1v;
            acc[4][0] += wb.x*x0; acc[4][1] += wb.x*x1v;
            acc[5][0] += wb.y*x0; acc[5][1] += wb.y*x1v;
            acc[6][0] += wb.z*x0; acc[6][1] += wb.z*x1v;
            acc[7][0] += wb.w*x0; acc[7][1] += wb.w*x1v;
        }
        const size_t pixg = (size_t)(row0 + (p0 >> 3)) * Ww + col0 + (p0 & 7);
#pragma unroll
        for (int i = 0; i < 8; i++) {
            const size_t g = (size_t)(b * Cc + o0 + i) * HW + pixg;
            float2 xr = *(const float2*)(xres + g);
            float2 ov = make_float2(xr.x + acc[i][0], xr.y + acc[i][1]);
            *(float2*)(xout + g) = ov;
        }
    }
}

// ---------------- launcher ----------------------------------------------------
extern "C" void kernel_launch(void* const* d_in, const int* in_sizes, int n_in,
                              void* d_out, int out_size)
{
    const float* x     = (const float*)d_in[0];
    const float* ln1w  = (const float*)d_in[1];
    const float* ln1b  = (const float*)d_in[2];
    const float* qkvw  = (const float*)d_in[3];
    const float* qkvdw = (const float*)d_in[4];
    const float* temp  = (const float*)d_in[5];
    const float* projw = (const float*)d_in[6];
    const float* projb = (const float*)d_in[7];
    const float* ln2w  = (const float*)d_in[8];
    const float* ln2b  = (const float*)d_in[9];
    const float* pinw  = (const float*)d_in[10];
    const float* dww   = (const float*)d_in[11];
    const float* poutw = (const float*)d_in[12];
    float* out = (float*)d_out;

    float *qkv, *qkv2, *x1, *mid, *y, *wq, *wp, *wo;
    cudaGetSymbolAddress((void**)&qkv,  g_qkv);
    cudaGetSymbolAddress((void**)&qkv2, g_qkv2);
    cudaGetSymbolAddress((void**)&x1,   g_x1);
    cudaGetSymbolAddress((void**)&mid,  g_mid);
    cudaGetSymbolAddress((void**)&y,    g_y);
    cudaGetSymbolAddress((void**)&wq,   g_wq);
    cudaGetSymbolAddress((void**)&wp,   g_wp);
    cudaGetSymbolAddress((void**)&wo,   g_wo);

    // weight prep: transpose + tf32
    k_prep<<<96, 256>>>(qkvw, pinw, poutw, wq, wp, wo);
    // LN1 + qkv 1x1
    k_ln_mma2<C3, 192><<<(Bz * HW) / 128, 256>>>(x, ln1w, ln1b, wq, qkv);
    // depthwise 3x3 on qkv
    k_dw4<C3><<<(Bz * C3 * HW / 4) / 256, 256>>>(qkv, qkvdw, qkv2);
    // window attention + proj + residual -> x1
    k_attn<<<Bz * 32 * 32, 256>>>(qkv2, temp, projw, projb, x, x1);
    // LN2 + pin 1x1
    k_ln_mma2<C2, 384><<<(Bz * HW) / 128, 256>>>(x1, ln2w, ln2b, wp, mid);
    // depthwise 3x3 + GELU gate
    k_dwgate4<<<(Bz * HID * HW / 4) / 256, 256>>>(mid, dww, y);
    // pout 1x1 + residual -> out
    k_pout2<<<(Bz * HW) / 64, 128>>>(y, wo, x1, out);
}

// round 4
// speedup vs baseline: 2.6846x; 1.1143x over previous
#include <cuda_runtime.h>
#include <math.h>
#include <stdint.h>

// Problem constants
#define Bz   4
#define Cc   64
#define Hh   256
#define Ww   256
#define HW   65536
#define HEADS 2
#define CH   32
#define WS   8
#define HID  170
#define C2   340
#define C3   192

// ---------------- scratch (device globals) ----------------
static __device__ float g_qkv [(size_t)Bz*C3*HW];
static __device__ float g_qkv2[(size_t)Bz*C3*HW];
static __device__ float g_x1  [(size_t)Bz*Cc*HW];
static __device__ float g_mid [(size_t)Bz*C2*HW];
static __device__ float g_y   [(size_t)Bz*HID*HW];
// pre-transposed tf32 weights: [k][o]
static __device__ float g_wq  [64 * 192];
static __device__ float g_wp  [64 * 384];
static __device__ float g_wo  [192 * 64];

// ---------------- helpers ----------------
__device__ __forceinline__ uint32_t f2tf32(float x) {
    uint32_t u;
    asm("cvt.rna.tf32.f32 %0, %1;" : "=r"(u) : "f"(x));
    return u;
}
__device__ __forceinline__ float tf32f(float x) { return __uint_as_float(f2tf32(x)); }

__device__ __forceinline__ void mma_tf32(float& c0, float& c1, float& c2, float& c3,
                                         uint32_t a0, uint32_t a1, uint32_t a2, uint32_t a3,
                                         uint32_t b0, uint32_t b1)
{
    asm volatile("mma.sync.aligned.m16n8k8.row.col.f32.tf32.tf32.f32 "
        "{%0,%1,%2,%3}, {%4,%5,%6,%7}, {%8,%9}, {%0,%1,%2,%3};"
        : "+f"(c0), "+f"(c1), "+f"(c2), "+f"(c3)
        : "r"(a0), "r"(a1), "r"(a2), "r"(a3), "r"(b0), "r"(b1));
}

#define SXS 68   // A-tile stride (=4 mod 32 -> conflict-free frag loads)
#define WSS 72
#define WSS32 40

// ---------------- K0: weight prep (transpose + tf32 convert) ------------------
__global__ void __launch_bounds__(256) k_prep(const float* __restrict__ qkvw,
        const float* __restrict__ pinw, const float* __restrict__ poutw,
        float* __restrict__ wq, float* __restrict__ wp, float* __restrict__ wo)
{
    const int t = blockIdx.x * 256 + threadIdx.x;
    if (t < 64 * 192) {
        const int k = t / 192, o = t % 192;
        wq[t] = tf32f(qkvw[o * 64 + k]);
    }
    if (t < 64 * 384) {
        const int k = t / 384, o = t % 384;
        wp[t] = (o < C2) ? tf32f(pinw[o * 64 + k]) : 0.f;
    }
    if (t < 192 * 64) {
        const int k = t / 64, o = t % 64;
        wo[t] = (k < HID) ? tf32f(poutw[o * HID + k]) : 0.f;
    }
}

// ---------------- K1/K4: fused LayerNorm + 1x1 conv, tf32 MMA -----------------
template<int COUT, int CPAD>
__global__ void __launch_bounds__(256) k_ln_mma2(const float* __restrict__ xin,
        const float* __restrict__ gw, const float* __restrict__ gb,
        const float* __restrict__ wT, float* __restrict__ out)
{
    __shared__ float sx[128 * SXS];
    __shared__ float ws[64 * WSS32];

    const int tid  = threadIdx.x;
    const int lane = tid & 31;
    const int warp = tid >> 5;
    const int p0   = blockIdx.x * 128;
    const int b    = p0 >> 16;
    const int hw0  = p0 & 65535;

    {
        const int pl = tid >> 1, half = tid & 1;
        const float* xp = xin + (size_t)(b * 64 + half * 32) * HW + hw0 + pl;
        float xv[32];
        float s = 0.f, s2 = 0.f;
#pragma unroll
        for (int i = 0; i < 32; i++) {
            xv[i] = xp[(size_t)i * HW];
            s += xv[i]; s2 += xv[i] * xv[i];
        }
        s  += __shfl_xor_sync(0xffffffffu, s, 1);
        s2 += __shfl_xor_sync(0xffffffffu, s2, 1);
        const float mu   = s * (1.f / 64.f);
        const float var  = fmaxf(s2 * (1.f / 64.f) - mu * mu, 0.f);
        const float rstd = rsqrtf(var + 1e-5f);
        float* sxp = sx + pl * SXS + half * 32;
#pragma unroll
        for (int i = 0; i < 32; i++) {
            const int c = half * 32 + i;
            sxp[i] = tf32f((xv[i] - mu) * rstd * __ldg(&gw[c]) + __ldg(&gb[c]));
        }
    }
    __syncthreads();

    const int r  = lane >> 2;
    const int c4 = lane & 3;
    const float* ap = sx + (warp * 16 + r) * SXS + c4;
    const float* bp = ws + c4 * WSS32 + r;

    uint32_t areg[8][4];
#pragma unroll
    for (int kk = 0; kk < 8; kk++) {
        const int kb = kk * 8;
        areg[kk][0] = __float_as_uint(ap[kb]);
        areg[kk][1] = __float_as_uint(ap[8 * SXS + kb]);
        areg[kk][2] = __float_as_uint(ap[kb + 4]);
        areg[kk][3] = __float_as_uint(ap[kb + 4 + 8 * SXS]);
    }

    const int pixb = hw0 + warp * 16 + r;
    const int NCH  = (COUT + 31) / 32;
    for (int chunk = 0; chunk < NCH; chunk++) {
        const int och = chunk * 32;
        __syncthreads();
        for (int idx = tid; idx < 64 * 32; idx += 256) {
            const int k = idx >> 5, o = idx & 31;
            ws[k * WSS32 + o] = wT[k * CPAD + och + o];
        }
        __syncthreads();

        float acc[4][4];
#pragma unroll
        for (int nt = 0; nt < 4; nt++)
#pragma unroll
            for (int j = 0; j < 4; j++) acc[nt][j] = 0.f;

#pragma unroll
        for (int kk = 0; kk < 8; kk++) {
            const int kb = kk * 8;
#pragma unroll
            for (int nt = 0; nt < 4; nt++) {
                const uint32_t b0 = __float_as_uint(bp[kb * WSS32 + nt * 8]);
                const uint32_t b1 = __float_as_uint(bp[(kb + 4) * WSS32 + nt * 8]);
                mma_tf32(acc[nt][0], acc[nt][1], acc[nt][2], acc[nt][3],
                         areg[kk][0], areg[kk][1], areg[kk][2], areg[kk][3], b0, b1);
            }
        }

#pragma unroll
        for (int nt = 0; nt < 4; nt++) {
            const int o = och + nt * 8 + 2 * c4;
            if ((COUT & 31) == 0 || o < COUT) {
                float* op = out + (size_t)(b * COUT + o) * HW + pixb;
                op[0]      = acc[nt][0];
                op[HW]     = acc[nt][1];
                op[8]      = acc[nt][2];
                op[HW + 8] = acc[nt][3];
            }
        }
    }
}

// ---------------- K6: pout (64 x 170) MMA + residual --------------------------
__global__ void __launch_bounds__(128) k_pout2(const float* __restrict__ y,
        const float* __restrict__ wT, const float* __restrict__ x1,
        float* __restrict__ out)
{
    __shared__ float sx[64 * SXS];
    __shared__ float ws[64 * WSS];

    const int tid  = threadIdx.x;
    const int lane = tid & 31;
    const int warp = tid >> 5;
    const int p0   = blockIdx.x * 64;
    const int b    = p0 >> 16;
    const int hw0  = p0 & 65535;

    const int r  = lane >> 2;
    const int c4 = lane & 3;
    const float* ap = sx + (warp * 16 + r) * SXS + c4;
    const float* bp = ws + c4 * WSS + r;

    float acc[8][4];
#pragma unroll
    for (int nt = 0; nt < 8; nt++)
#pragma unroll
        for (int j = 0; j < 4; j++) acc[nt][j] = 0.f;

    for (int kc = 0; kc < 192; kc += 64) {
        __syncthreads();
        {
            const int px = tid & 63, kh = tid >> 6;
            float* sxp = sx + px * SXS + kh * 32;
            const float* yp = y + (size_t)(b * HID + kc + kh * 32) * HW + hw0 + px;
#pragma unroll
            for (int j = 0; j < 32; j++) {
                const int gk = kc + kh * 32 + j;
                sxp[j] = (gk < HID) ? tf32f(yp[(size_t)j * HW]) : 0.f;
            }
        }
        for (int idx = tid; idx < 64 * 64; idx += 128) {
            const int k = idx >> 6, o = idx & 63;
            ws[k * WSS + o] = wT[(kc + k) * 64 + o];
        }
        __syncthreads();

#pragma unroll
        for (int kk = 0; kk < 8; kk++) {
            const int kb = kk * 8;
            const uint32_t a0 = __float_as_uint(ap[kb]);
            const uint32_t a1 = __float_as_uint(ap[8 * SXS + kb]);
            const uint32_t a2 = __float_as_uint(ap[kb + 4]);
            const uint32_t a3 = __float_as_uint(ap[kb + 4 + 8 * SXS]);
#pragma unroll
            for (int nt = 0; nt < 8; nt++) {
                const uint32_t b0 = __float_as_uint(bp[kb * WSS + nt * 8]);
                const uint32_t b1 = __float_as_uint(bp[(kb + 4) * WSS + nt * 8]);
                mma_tf32(acc[nt][0], acc[nt][1], acc[nt][2], acc[nt][3],
                         a0, a1, a2, a3, b0, b1);
            }
        }
    }

    const int pixb = hw0 + warp * 16 + r;
#pragma unroll
    for (int nt = 0; nt < 8; nt++) {
        const int o = nt * 8 + 2 * c4;
        const size_t g = (size_t)(b * 64 + o) * HW + pixb;
        out[g]          = x1[g]          + acc[nt][0];
        out[g + HW]     = x1[g + HW]     + acc[nt][1];
        out[g + 8]      = x1[g + 8]      + acc[nt][2];
        out[g + HW + 8] = x1[g + HW + 8] + acc[nt][3];
    }
}

// ---------------- K2/K5: depthwise 3x3 (4-wide vectorized) --------------------
__device__ __forceinline__ void dw4(const float* __restrict__ ip, int h, int w0,
                                    const float* wk, float* acc)
{
#pragma unroll
    for (int kh = 0; kh < 3; kh++) {
        const int hh = h + kh - 1;
        if ((unsigned)hh >= 256u) continue;
        const float* rp = ip + hh * Ww;
        float4 a = *(const float4*)(rp + w0);
        float rl = (w0 > 0)   ? rp[w0 - 1] : 0.f;
        float rr = (w0 < 252) ? rp[w0 + 4] : 0.f;
        float rv[6] = { rl, a.x, a.y, a.z, a.w, rr };
        const float k0 = wk[kh * 3], k1 = wk[kh * 3 + 1], k2 = wk[kh * 3 + 2];
#pragma unroll
        for (int j = 0; j < 4; j++)
            acc[j] += k0 * rv[j] + k1 * rv[j + 1] + k2 * rv[j + 2];
    }
}

template<int CHAN>
__global__ void __launch_bounds__(256) k_dw4(const float* __restrict__ in,
        const float* __restrict__ wt, float* __restrict__ out)
{
    const int idx = blockIdx.x * 256 + threadIdx.x;
    const int hwq = idx & 16383;
    const int cb  = idx >> 14;
    const int ch  = cb % CHAN;
    const int h = hwq >> 6, w0 = (hwq & 63) * 4;
    float wk[9];
#pragma unroll
    for (int j = 0; j < 9; j++) wk[j] = __ldg(&wt[ch * 9 + j]);
    const float* ip = in + ((size_t)cb << 16);
    float acc[4] = {0.f, 0.f, 0.f, 0.f};
    dw4(ip, h, w0, wk, acc);
    *(float4*)(out + (size_t)idx * 4) = make_float4(acc[0], acc[1], acc[2], acc[3]);
}

__global__ void __launch_bounds__(256) k_dwgate4(const float* __restrict__ in,
        const float* __restrict__ wt, float* __restrict__ out)
{
    const int idx = blockIdx.x * 256 + threadIdx.x;
    const int hwq = idx & 16383;
    const int cb  = idx >> 14;
    const int ch  = cb % HID;
    const int b   = cb / HID;
    const int h = hwq >> 6, w0 = (hwq & 63) * 4;

    float w1[9], w2[9];
#pragma unroll
    for (int j = 0; j < 9; j++) w1[j] = __ldg(&wt[ch * 9 + j]);
#pragma unroll
    for (int j = 0; j < 9; j++) w2[j] = __ldg(&wt[(ch + HID) * 9 + j]);

    const float* ip1 = in + (size_t)(b * C2 + ch) * HW;
    const float* ip2 = ip1 + (size_t)HID * HW;
    float a1[4] = {0,0,0,0}, a2[4] = {0,0,0,0};
    dw4(ip1, h, w0, w1, a1);
    dw4(ip2, h, w0, w2, a2);
    float o[4];
#pragma unroll
    for (int j = 0; j < 4; j++) {
        const float ge = 0.5f * a1[j] * (1.0f + erff(a1[j] * 0.70710678118654752f));
        o[j] = ge * a2[j];
    }
    *(float4*)(out + (size_t)idx * 4) = make_float4(o[0], o[1], o[2], o[3]);
}

// ---------------- K3: fused window attention + proj + residual, tf32 MMA ------
// smem strides: 68 (=4 mod 32) and 36 (=4 mod 32): frag loads conflict-free.
#define QP 68
#define AP 36
__global__ void __launch_bounds__(256) k_attn_mma(const float* __restrict__ qkv,
        const float* __restrict__ temp, const float* __restrict__ pw,
        const float* __restrict__ pb, const float* __restrict__ xres,
        float* __restrict__ xout)
{
    __shared__ float sq[64 * QP];    // q (scaled tf32) -> attn-out [ch][px] tf32
    __shared__ float sk[64 * QP];    // k (scaled tf32) -> v (tf32) -> proj W
    __shared__ float sat[64 * AP];   // attn logits -> softmax weights (tf32)

    const int tid  = threadIdx.x;
    const int lane = tid & 31;
    const int w    = tid >> 5;
    const int r    = lane >> 2;
    const int c4   = lane & 3;

    const int win  = blockIdx.x;
    const int b    = win >> 10;
    const int row0 = ((win >> 5) & 31) * WS;
    const int col0 = (win & 31) * WS;

    // ---- P1: gather q,k (fp32)
    for (int i = tid; i < 8192; i += 256) {
        const int s = i >> 12;
        const int rr = i & 4095;
        const int head = rr >> 11, ci = (rr >> 6) & 31, d = rr & 63;
        const int ch = (s * HEADS + head) * CH + ci;
        const size_t g = (size_t)(b * C3 + ch) * HW
                       + (size_t)(row0 + (d >> 3)) * Ww + col0 + (d & 7);
        float* dst = (s == 0) ? sq : sk;
        dst[(head * 32 + ci) * QP + d] = qkv[g];
    }
    __syncthreads();

    // ---- P2: l2 norms + scale + tf32 (2 threads per row; q rows also * temp)
    {
        const int rowi = tid >> 1, half = tid & 1;
        float* rp = ((rowi < 64) ? sq + rowi * QP : sk + (rowi - 64) * QP) + half * 32;
        float ss = 0.f;
#pragma unroll
        for (int j = 0; j < 8; j++) {
            float4 v = *(const float4*)(rp + j * 4);
            ss += v.x * v.x + v.y * v.y + v.z * v.z + v.w * v.w;
        }
        ss += __shfl_xor_sync(0xffffffffu, ss, 1);
        float sc = 1.f / fmaxf(sqrtf(ss), 1e-12f);
        if (rowi < 64) sc *= __ldg(&temp[rowi >> 5]);
#pragma unroll
        for (int j = 0; j < 8; j++) {
            float4 v = *(const float4*)(rp + j * 4);
            v.x = tf32f(v.x * sc); v.y = tf32f(v.y * sc);
            v.z = tf32f(v.z * sc); v.w = tf32f(v.w * sc);
            *(float4*)(rp + j * 4) = v;
        }
    }
    __syncthreads();

    // ---- P3: logits = q @ k^T  (per-warp: head, mtile, n-half)
    {
        const int h  = w >> 2, mt = (w >> 1) & 1, nh = w & 1;
        const float* aq = sq + (h * 32 + mt * 16 + r) * QP + c4;
        uint32_t a[8][4];
#pragma unroll
        for (int kk = 0; kk < 8; kk++) {
            const int kb = kk * 8;
            a[kk][0] = __float_as_uint(aq[kb]);
            a[kk][1] = __float_as_uint(aq[8 * QP + kb]);
            a[kk][2] = __float_as_uint(aq[kb + 4]);
            a[kk][3] = __float_as_uint(aq[8 * QP + kb + 4]);
        }
#pragma unroll
        for (int nt = 0; nt < 2; nt++) {
            const int e0 = nh * 16 + nt * 8;
            const float* bk = sk + (h * 32 + e0 + r) * QP + c4;
            float c0 = 0.f, c1 = 0.f, c2 = 0.f, c3 = 0.f;
#pragma unroll
            for (int kk = 0; kk < 8; kk++) {
                const int kb = kk * 8;
                mma_tf32(c0, c1, c2, c3, a[kk][0], a[kk][1], a[kk][2], a[kk][3],
                         __float_as_uint(bk[kb]), __float_as_uint(bk[kb + 4]));
            }
            float* so = sat + (h * 32 + mt * 16 + r) * AP + e0 + 2 * c4;
            *(float2*)so            = make_float2(c0, c1);
            *(float2*)(so + 8 * AP) = make_float2(c2, c3);
        }
    }
    __syncthreads();

    // ---- P5: load v (tf32) into sk
    for (int i = tid; i < 4096; i += 256) {
        const int head = i >> 11, ci = (i >> 6) & 31, d = i & 63;
        const int ch = (2 * HEADS + head) * CH + ci;
        const size_t g = (size_t)(b * C3 + ch) * HW
                       + (size_t)(row0 + (d >> 3)) * Ww + col0 + (d & 7);
        sk[(head * 32 + ci) * QP + d] = tf32f(qkv[g]);
    }
    // ---- P4: softmax (4 threads/row), write back tf32
    {
        const int rowi = tid >> 2, sub = tid & 3;
        float* rp = sat + rowi * AP + sub * 8;
        float4 v0 = *(const float4*)rp;
        float4 v1 = *(const float4*)(rp + 4);
        float m = fmaxf(fmaxf(fmaxf(v0.x, v0.y), fmaxf(v0.z, v0.w)),
                        fmaxf(fmaxf(v1.x, v1.y), fmaxf(v1.z, v1.w)));
        m = fmaxf(m, __shfl_xor_sync(0xffffffffu, m, 1));
        m = fmaxf(m, __shfl_xor_sync(0xffffffffu, m, 2));
        float e[8];
        e[0] = __expf(v0.x - m); e[1] = __expf(v0.y - m);
        e[2] = __expf(v0.z - m); e[3] = __expf(v0.w - m);
        e[4] = __expf(v1.x - m); e[5] = __expf(v1.y - m);
        e[6] = __expf(v1.z - m); e[7] = __expf(v1.w - m);
        float s = e[0]+e[1]+e[2]+e[3]+e[4]+e[5]+e[6]+e[7];
        s += __shfl_xor_sync(0xffffffffu, s, 1);
        s += __shfl_xor_sync(0xffffffffu, s, 2);
        const float inv = 1.f / s;
        *(float4*)rp       = make_float4(tf32f(e[0]*inv), tf32f(e[1]*inv),
                                         tf32f(e[2]*inv), tf32f(e[3]*inv));
        *(float4*)(rp + 4) = make_float4(tf32f(e[4]*inv), tf32f(e[5]*inv),
                                         tf32f(e[6]*inv), tf32f(e[7]*inv));
    }
    __syncthreads();

    // ---- P6: attn-out = softmax @ v  -> sq as [channel][pixel] tf32
    {
        const int h  = w >> 2, mt = (w >> 1) & 1, nq = w & 1;
        const float* aa = sat + (h * 32 + mt * 16 + r) * AP + c4;
        uint32_t a[4][4];
#pragma unroll
        for (int kk = 0; kk < 4; kk++) {
            const int kb = kk * 8;
            a[kk][0] = __float_as_uint(aa[kb]);
            a[kk][1] = __float_as_uint(aa[8 * AP + kb]);
            a[kk][2] = __float_as_uint(aa[kb + 4]);
            a[kk][3] = __float_as_uint(aa[8 * AP + kb + 4]);
        }
        float acc[4][4];
#pragma unroll
        for (int nt = 0; nt < 4; nt++)
#pragma unroll
            for (int j = 0; j < 4; j++) acc[nt][j] = 0.f;
#pragma unroll
        for (int nt = 0; nt < 4; nt++) {
            const int d0 = nq * 32 + nt * 8;
            const float* bv = sk + (h * 32 + c4) * QP + d0 + r;
#pragma unroll
            for (int kk = 0; kk < 4; kk++) {
                const int kb = kk * 8;
                mma_tf32(acc[nt][0], acc[nt][1], acc[nt][2], acc[nt][3],
                         a[kk][0], a[kk][1], a[kk][2], a[kk][3],
                         __float_as_uint(bv[kb * QP]),
                         __float_as_uint(bv[(kb + 4) * QP]));
            }
        }
        __syncthreads();   // all reads of sq (q) done in P3; safe to overwrite
#pragma unroll
        for (int nt = 0; nt < 4; nt++) {
            const int d0 = nq * 32 + nt * 8;
            float* so = sq + (h * 32 + mt * 16 + r) * QP + d0 + 2 * c4;
            *(float2*)so           = make_float2(tf32f(acc[nt][0]), tf32f(acc[nt][1]));
            *(float2*)(so + 8 * QP) = make_float2(tf32f(acc[nt][2]), tf32f(acc[nt][3]));
        }
    }
    __syncthreads();

    // ---- P7: stage proj weights [o][k] tf32 into sk
    for (int idx = tid; idx < 64 * 64; idx += 256) {
        const int o = idx >> 6, k = idx & 63;
        sk[o * QP + k] = tf32f(pw[idx]);
    }
    __syncthreads();

    // ---- P8: proj MMA + bias + residual
    {
        const int mt = w >> 1, nh = w & 1;
        const float* aw = sk + (mt * 16 + r) * QP + c4;
        uint32_t a[8][4];
#pragma unroll
        for (int kk = 0; kk < 8; kk++) {
            const int kb = kk * 8;
            a[kk][0] = __float_as_uint(aw[kb]);
            a[kk][1] = __float_as_uint(aw[8 * QP + kb]);
            a[kk][2] = __float_as_uint(aw[kb + 4]);
            a[kk][3] = __float_as_uint(aw[8 * QP + kb + 4]);
        }
        const int o1 = mt * 16 + r, o2 = o1 + 8;
        const float bv1 = __ldg(&pb[o1]), bv2 = __ldg(&pb[o2]);
#pragma unroll
        for (int nt = 0; nt < 4; nt++) {
            const int p0 = nh * 32 + nt * 8;
            const float* bx = sq + c4 * QP + p0 + r;
            float c0 = 0.f, c1 = 0.f, c2 = 0.f, c3 = 0.f;
#pragma unroll
            for (int kk = 0; kk < 8; kk++) {
                const int kb = kk * 8;
                mma_tf32(c0, c1, c2, c3, a[kk][0], a[kk][1], a[kk][2], a[kk][3],
                         __float_as_uint(bx[kb * QP]),
                         __float_as_uint(bx[(kb + 4) * QP]));
            }
            const int p = p0 + 2 * c4;
            const size_t pixg = (size_t)(row0 + (p >> 3)) * Ww + col0 + (p & 7);
            {
                const size_t g = (size_t)(b * Cc + o1) * HW + pixg;
                float2 xr = *(const float2*)(xres + g);
                *(float2*)(xout + g) = make_float2(xr.x + c0 + bv1, xr.y + c1 + bv1);
            }
            {
                const size_t g = (size_t)(b * Cc + o2) * HW + pixg;
                float2 xr = *(const float2*)(xres + g);
                *(float2*)(xout + g) = make_float2(xr.x + c2 + bv2, xr.y + c3 + bv2);
            }
        }
    }
}

// ---------------- launcher ----------------------------------------------------
extern "C" void kernel_launch(void* const* d_in, const int* in_sizes, int n_in,
                              void* d_out, int out_size)
{
    const float* x     = (const float*)d_in[0];
    const float* ln1w  = (const float*)d_in[1];
    const float* ln1b  = (const float*)d_in[2];
    const float* qkvw  = (const float*)d_in[3];
    const float* qkvdw = (const float*)d_in[4];
    const float* temp  = (const float*)d_in[5];
    const float* projw = (const float*)d_in[6];
    const float* projb = (const float*)d_in[7];
    const float* ln2w  = (const float*)d_in[8];
    const float* ln2b  = (const float*)d_in[9];
    const float* pinw  = (const float*)d_in[10];
    const float* dww   = (const float*)d_in[11];
    const float* poutw = (const float*)d_in[12];
    float* out = (float*)d_out;

    float *qkv, *qkv2, *x1, *mid, *y, *wq, *wp, *wo;
    cudaGetSymbolAddress((void**)&qkv,  g_qkv);
    cudaGetSymbolAddress((void**)&qkv2, g_qkv2);
    cudaGetSymbolAddress((void**)&x1,   g_x1);
    cudaGetSymbolAddress((void**)&mid,  g_mid);
    cudaGetSymbolAddress((void**)&y,    g_y);
    cudaGetSymbolAddress((void**)&wq,   g_wq);
    cudaGetSymbolAddress((void**)&wp,   g_wp);
    cudaGetSymbolAddress((void**)&wo,   g_wo);

    k_prep<<<96, 256>>>(qkvw, pinw, poutw, wq, wp, wo);
    k_ln_mma2<C3, 192><<<(Bz * HW) / 128, 256>>>(x, ln1w, ln1b, wq, qkv);
    k_dw4<C3><<<(Bz * C3 * HW / 4) / 256, 256>>>(qkv, qkvdw, qkv2);
    k_attn_mma<<<Bz * 32 * 32, 256>>>(qkv2, temp, projw, projb, x, x1);
    k_ln_mma2<C2, 384><<<(Bz * HW) / 128, 256>>>(x1, ln2w, ln2b, wp, mid);
    k_dwgate4<<<(Bz * HID * HW / 4) / 256, 256>>>(mid, dww, y);
    k_pout2<<<(Bz * HW) / 64, 128>>>(y, wo, x1, out);
}

// round 5
// speedup vs baseline: 3.0132x; 1.1224x over previous
#include <cuda_runtime.h>
#include <cuda_bf16.h>
#include <math.h>
#include <stdint.h>

typedef __nv_bfloat16 bf16;

// Problem constants
#define Bz   4
#define Cc   64
#define Hh   256
#define Ww   256
#define HW   65536
#define HEADS 2
#define CH   32
#define WS   8
#define HID  170
#define C2   340
#define C3   192

// ---------------- scratch (device globals) ----------------
static __device__ bf16  g_qkv [(size_t)Bz*C3*HW];
static __device__ bf16  g_qkv2[(size_t)Bz*C3*HW];
static __device__ float g_x1  [(size_t)Bz*Cc*HW];       // residual carrier: fp32
static __device__ bf16  g_mid [(size_t)Bz*C2*HW];
static __device__ bf16  g_y   [(size_t)Bz*HID*HW];
// pre-transposed tf32 weights: [k][o]
static __device__ float g_wq  [64 * 192];
static __device__ float g_wp  [64 * 384];
static __device__ float g_wo  [192 * 64];

// ---------------- helpers ----------------
__device__ __forceinline__ uint32_t f2tf32(float x) {
    uint32_t u;
    asm("cvt.rna.tf32.f32 %0, %1;" : "=r"(u) : "f"(x));
    return u;
}
__device__ __forceinline__ float tf32f(float x) { return __uint_as_float(f2tf32(x)); }

__device__ __forceinline__ void mma_tf32(float& c0, float& c1, float& c2, float& c3,
                                         uint32_t a0, uint32_t a1, uint32_t a2, uint32_t a3,
                                         uint32_t b0, uint32_t b1)
{
    asm volatile("mma.sync.aligned.m16n8k8.row.col.f32.tf32.tf32.f32 "
        "{%0,%1,%2,%3}, {%4,%5,%6,%7}, {%8,%9}, {%0,%1,%2,%3};"
        : "+f"(c0), "+f"(c1), "+f"(c2), "+f"(c3)
        : "r"(a0), "r"(a1), "r"(a2), "r"(a3), "r"(b0), "r"(b1));
}

// unpack 8 bf16 (uint4) -> 8 floats
__device__ __forceinline__ void bf8_to_f(const uint4& u, float* f) {
    float2 t;
    t = __bfloat1622float2(*reinterpret_cast<const __nv_bfloat162*>(&u.x)); f[0]=t.x; f[1]=t.y;
    t = __bfloat1622float2(*reinterpret_cast<const __nv_bfloat162*>(&u.y)); f[2]=t.x; f[3]=t.y;
    t = __bfloat1622float2(*reinterpret_cast<const __nv_bfloat162*>(&u.z)); f[4]=t.x; f[5]=t.y;
    t = __bfloat1622float2(*reinterpret_cast<const __nv_bfloat162*>(&u.w)); f[6]=t.x; f[7]=t.y;
}
__device__ __forceinline__ uint4 f_to_bf8(const float* f) {
    uint4 u;
    *reinterpret_cast<__nv_bfloat162*>(&u.x) = __float22bfloat162_rn(make_float2(f[0], f[1]));
    *reinterpret_cast<__nv_bfloat162*>(&u.y) = __float22bfloat162_rn(make_float2(f[2], f[3]));
    *reinterpret_cast<__nv_bfloat162*>(&u.z) = __float22bfloat162_rn(make_float2(f[4], f[5]));
    *reinterpret_cast<__nv_bfloat162*>(&u.w) = __float22bfloat162_rn(make_float2(f[6], f[7]));
    return u;
}

#define SXS 68   // A-tile stride (=4 mod 32 -> conflict-free frag loads)
#define WSS 72
#define WSS32 40

// ---------------- K0: weight prep (transpose + tf32 convert) ------------------
__global__ void __launch_bounds__(256) k_prep(const float* __restrict__ qkvw,
        const float* __restrict__ pinw, const float* __restrict__ poutw,
        float* __restrict__ wq, float* __restrict__ wp, float* __restrict__ wo)
{
    const int t = blockIdx.x * 256 + threadIdx.x;
    if (t < 64 * 192) {
        const int k = t / 192, o = t % 192;
        wq[t] = tf32f(qkvw[o * 64 + k]);
    }
    if (t < 64 * 384) {
        const int k = t / 384, o = t % 384;
        wp[t] = (o < C2) ? tf32f(pinw[o * 64 + k]) : 0.f;
    }
    if (t < 192 * 64) {
        const int k = t / 64, o = t % 64;
        wo[t] = (k < HID) ? tf32f(poutw[o * HID + k]) : 0.f;
    }
}

// ---------------- K1/K4: fused LayerNorm + 1x1 conv, tf32 MMA, bf16 out -------
template<int COUT, int CPAD>
__global__ void __launch_bounds__(256) k_ln_mma2(const float* __restrict__ xin,
        const float* __restrict__ gw, const float* __restrict__ gb,
        const float* __restrict__ wT, bf16* __restrict__ out)
{
    __shared__ float sx[128 * SXS];
    __shared__ float ws[64 * WSS32];

    const int tid  = threadIdx.x;
    const int lane = tid & 31;
    const int warp = tid >> 5;
    const int p0   = blockIdx.x * 128;
    const int b    = p0 >> 16;
    const int hw0  = p0 & 65535;

    {
        const int pl = tid >> 1, half = tid & 1;
        const float* xp = xin + (size_t)(b * 64 + half * 32) * HW + hw0 + pl;
        float xv[32];
        float s = 0.f, s2 = 0.f;
#pragma unroll
        for (int i = 0; i < 32; i++) {
            xv[i] = xp[(size_t)i * HW];
            s += xv[i]; s2 += xv[i] * xv[i];
        }
        s  += __shfl_xor_sync(0xffffffffu, s, 1);
        s2 += __shfl_xor_sync(0xffffffffu, s2, 1);
        const float mu   = s * (1.f / 64.f);
        const float var  = fmaxf(s2 * (1.f / 64.f) - mu * mu, 0.f);
        const float rstd = rsqrtf(var + 1e-5f);
        float* sxp = sx + pl * SXS + half * 32;
#pragma unroll
        for (int i = 0; i < 32; i++) {
            const int c = half * 32 + i;
            sxp[i] = tf32f((xv[i] - mu) * rstd * __ldg(&gw[c]) + __ldg(&gb[c]));
        }
    }
    __syncthreads();

    const int r  = lane >> 2;
    const int c4 = lane & 3;
    const float* ap = sx + (warp * 16 + r) * SXS + c4;
    const float* bp = ws + c4 * WSS32 + r;

    uint32_t areg[8][4];
#pragma unroll
    for (int kk = 0; kk < 8; kk++) {
        const int kb = kk * 8;
        areg[kk][0] = __float_as_uint(ap[kb]);
        areg[kk][1] = __float_as_uint(ap[8 * SXS + kb]);
        areg[kk][2] = __float_as_uint(ap[kb + 4]);
        areg[kk][3] = __float_as_uint(ap[kb + 4 + 8 * SXS]);
    }

    const int pixb = hw0 + warp * 16 + r;
    const int NCH  = (COUT + 31) / 32;
    for (int chunk = 0; chunk < NCH; chunk++) {
        const int och = chunk * 32;
        __syncthreads();
        for (int idx = tid; idx < 64 * 32; idx += 256) {
            const int k = idx >> 5, o = idx & 31;
            ws[k * WSS32 + o] = wT[k * CPAD + och + o];
        }
        __syncthreads();

        float acc[4][4];
#pragma unroll
        for (int nt = 0; nt < 4; nt++)
#pragma unroll
            for (int j = 0; j < 4; j++) acc[nt][j] = 0.f;

#pragma unroll
        for (int kk = 0; kk < 8; kk++) {
            const int kb = kk * 8;
#pragma unroll
            for (int nt = 0; nt < 4; nt++) {
                const uint32_t b0 = __float_as_uint(bp[kb * WSS32 + nt * 8]);
                const uint32_t b1 = __float_as_uint(bp[(kb + 4) * WSS32 + nt * 8]);
                mma_tf32(acc[nt][0], acc[nt][1], acc[nt][2], acc[nt][3],
                         areg[kk][0], areg[kk][1], areg[kk][2], areg[kk][3], b0, b1);
            }
        }

#pragma unroll
        for (int nt = 0; nt < 4; nt++) {
            const int o = och + nt * 8 + 2 * c4;
            if ((COUT & 31) == 0 || o < COUT) {
                bf16* op = out + (size_t)(b * COUT + o) * HW + pixb;
                op[0]      = __float2bfloat16(acc[nt][0]);
                op[HW]     = __float2bfloat16(acc[nt][1]);
                op[8]      = __float2bfloat16(acc[nt][2]);
                op[HW + 8] = __float2bfloat16(acc[nt][3]);
            }
        }
    }
}

// ---------------- K6: pout (64 x 170) MMA + residual --------------------------
__global__ void __launch_bounds__(128) k_pout2(const bf16* __restrict__ y,
        const float* __restrict__ wT, const float* __restrict__ x1,
        float* __restrict__ out)
{
    __shared__ float sx[64 * SXS];
    __shared__ float ws[64 * WSS];

    const int tid  = threadIdx.x;
    const int lane = tid & 31;
    const int warp = tid >> 5;
    const int p0   = blockIdx.x * 64;
    const int b    = p0 >> 16;
    const int hw0  = p0 & 65535;

    const int r  = lane >> 2;
    const int c4 = lane & 3;
    const float* ap = sx + (warp * 16 + r) * SXS + c4;
    const float* bp = ws + c4 * WSS + r;

    float acc[8][4];
#pragma unroll
    for (int nt = 0; nt < 8; nt++)
#pragma unroll
        for (int j = 0; j < 4; j++) acc[nt][j] = 0.f;

    for (int kc = 0; kc < 192; kc += 64) {
        __syncthreads();
        {
            const int px = tid & 63, kh = tid >> 6;
            float* sxp = sx + px * SXS + kh * 32;
            const bf16* yp = y + (size_t)(b * HID + kc + kh * 32) * HW + hw0 + px;
#pragma unroll
            for (int j = 0; j < 32; j++) {
                const int gk = kc + kh * 32 + j;
                sxp[j] = (gk < HID) ? tf32f(__bfloat162float(yp[(size_t)j * HW])) : 0.f;
            }
        }
        for (int idx = tid; idx < 64 * 64; idx += 128) {
            const int k = idx >> 6, o = idx & 63;
            ws[k * WSS + o] = wT[(kc + k) * 64 + o];
        }
        __syncthreads();

#pragma unroll
        for (int kk = 0; kk < 8; kk++) {
            const int kb = kk * 8;
            const uint32_t a0 = __float_as_uint(ap[kb]);
            const uint32_t a1 = __float_as_uint(ap[8 * SXS + kb]);
            const uint32_t a2 = __float_as_uint(ap[kb + 4]);
            const uint32_t a3 = __float_as_uint(ap[kb + 4 + 8 * SXS]);
#pragma unroll
            for (int nt = 0; nt < 8; nt++) {
                const uint32_t b0 = __float_as_uint(bp[kb * WSS + nt * 8]);
                const uint32_t b1 = __float_as_uint(bp[(kb + 4) * WSS + nt * 8]);
                mma_tf32(acc[nt][0], acc[nt][1], acc[nt][2], acc[nt][3],
                         a0, a1, a2, a3, b0, b1);
            }
        }
    }

    const int pixb = hw0 + warp * 16 + r;
#pragma unroll
    for (int nt = 0; nt < 8; nt++) {
        const int o = nt * 8 + 2 * c4;
        const size_t g = (size_t)(b * 64 + o) * HW + pixb;
        out[g]          = x1[g]          + acc[nt][0];
        out[g + HW]     = x1[g + HW]     + acc[nt][1];
        out[g + 8]      = x1[g + 8]      + acc[nt][2];
        out[g + HW + 8] = x1[g + HW + 8] + acc[nt][3];
    }
}

// ---------------- K2/K5: depthwise 3x3, bf16, 8-wide ---------------------------
__device__ __forceinline__ void dw8(const bf16* __restrict__ ip, int h, int w0,
                                    const float* wk, float* acc)
{
#pragma unroll
    for (int kh = 0; kh < 3; kh++) {
        const int hh = h + kh - 1;
        if ((unsigned)hh >= 256u) continue;
        const bf16* rp = ip + hh * Ww + w0;
        float rv[10];
        rv[0] = (w0 > 0)   ? __bfloat162float(rp[-1]) : 0.f;
        rv[9] = (w0 < 248) ? __bfloat162float(rp[8])  : 0.f;
        uint4 u = *(const uint4*)rp;
        bf8_to_f(u, rv + 1);
        const float k0 = wk[kh * 3], k1 = wk[kh * 3 + 1], k2 = wk[kh * 3 + 2];
#pragma unroll
        for (int j = 0; j < 8; j++)
            acc[j] += k0 * rv[j] + k1 * rv[j + 1] + k2 * rv[j + 2];
    }
}

template<int CHAN>
__global__ void __launch_bounds__(256) k_dw8(const bf16* __restrict__ in,
        const float* __restrict__ wt, bf16* __restrict__ out)
{
    const int idx = blockIdx.x * 256 + threadIdx.x;      // over B*CHAN*HW/8
    const int hwo = idx & 8191;
    const int cb  = idx >> 13;
    const int ch  = cb % CHAN;
    const int h = hwo >> 5, w0 = (hwo & 31) * 8;
    float wk[9];
#pragma unroll
    for (int j = 0; j < 9; j++) wk[j] = __ldg(&wt[ch * 9 + j]);
    const bf16* ip = in + ((size_t)cb << 16);
    float acc[8] = {0,0,0,0,0,0,0,0};
    dw8(ip, h, w0, wk, acc);
    *(uint4*)(out + (size_t)idx * 8) = f_to_bf8(acc);
}

__global__ void __launch_bounds__(256) k_dwgate8(const bf16* __restrict__ in,
        const float* __restrict__ wt, bf16* __restrict__ out)
{
    const int idx = blockIdx.x * 256 + threadIdx.x;      // over B*HID*HW/8
    const int hwo = idx & 8191;
    const int cb  = idx >> 13;
    const int ch  = cb % HID;
    const int b   = cb / HID;
    const int h = hwo >> 5, w0 = (hwo & 31) * 8;

    float w1[9], w2[9];
#pragma unroll
    for (int j = 0; j < 9; j++) w1[j] = __ldg(&wt[ch * 9 + j]);
#pragma unroll
    for (int j = 0; j < 9; j++) w2[j] = __ldg(&wt[(ch + HID) * 9 + j]);

    const bf16* ip1 = in + (size_t)(b * C2 + ch) * HW;
    const bf16* ip2 = ip1 + (size_t)HID * HW;
    float a1[8] = {0,0,0,0,0,0,0,0}, a2[8] = {0,0,0,0,0,0,0,0};
    dw8(ip1, h, w0, w1, a1);
    dw8(ip2, h, w0, w2, a2);
    float o[8];
#pragma unroll
    for (int j = 0; j < 8; j++) {
        const float ge = 0.5f * a1[j] * (1.0f + erff(a1[j] * 0.70710678118654752f));
        o[j] = ge * a2[j];
    }
    *(uint4*)(out + (size_t)idx * 8) = f_to_bf8(o);
}

// ---------------- K3: fused window attention + proj + residual, tf32 MMA ------
#define QP 68
#define AP 36
__global__ void __launch_bounds__(256, 4) k_attn_mma(const bf16* __restrict__ qkv,
        const float* __restrict__ temp, const float* __restrict__ pw,
        const float* __restrict__ pb, const float* __restrict__ xres,
        float* __restrict__ xout)
{
    __shared__ float sq[64 * QP];    // q (scaled tf32) -> attn-out [ch][px] tf32
    __shared__ float sk[64 * QP];    // k (scaled tf32) -> v (tf32) -> proj W
    __shared__ float sat[64 * AP];   // attn logits -> softmax weights (tf32)

    const int tid  = threadIdx.x;
    const int lane = tid & 31;
    const int w    = tid >> 5;
    const int r    = lane >> 2;
    const int c4   = lane & 3;

    const int win  = blockIdx.x;
    const int b    = win >> 10;
    const int row0 = ((win >> 5) & 31) * WS;
    const int col0 = (win & 31) * WS;

    // ---- P1: gather q,k (bf16 strips of 8 = one uint4)
    for (int i = tid; i < 1024; i += 256) {
        const int s = i >> 9, ch = (i >> 3) & 63, row = i & 7;
        const bf16* src = qkv + (size_t)(b * C3 + s * 64 + ch) * HW
                        + (size_t)(row0 + row) * Ww + col0;
        float f[8];
        bf8_to_f(*(const uint4*)src, f);
        float* dst = ((s == 0) ? sq : sk) + ch * QP + row * 8;
        *(float4*)dst       = make_float4(f[0], f[1], f[2], f[3]);
        *(float4*)(dst + 4) = make_float4(f[4], f[5], f[6], f[7]);
    }
    __syncthreads();

    // ---- P2: l2 norms + scale + tf32 (2 threads per row; q rows also * temp)
    {
        const int rowi = tid >> 1, half = tid & 1;
        float* rp = ((rowi < 64) ? sq + rowi * QP : sk + (rowi - 64) * QP) + half * 32;
        float ss = 0.f;
#pragma unroll
        for (int j = 0; j < 8; j++) {
            float4 v = *(const float4*)(rp + j * 4);
            ss += v.x * v.x + v.y * v.y + v.z * v.z + v.w * v.w;
        }
        ss += __shfl_xor_sync(0xffffffffu, ss, 1);
        float sc = 1.f / fmaxf(sqrtf(ss), 1e-12f);
        if (rowi < 64) sc *= __ldg(&temp[rowi >> 5]);
#pragma unroll
        for (int j = 0; j < 8; j++) {
            float4 v = *(const float4*)(rp + j * 4);
            v.x = tf32f(v.x * sc); v.y = tf32f(v.y * sc);
            v.z = tf32f(v.z * sc); v.w = tf32f(v.w * sc);
            *(float4*)(rp + j * 4) = v;
        }
    }
    __syncthreads();

    // ---- P3: logits = q @ k^T
    {
        const int h  = w >> 2, mt = (w >> 1) & 1, nh = w & 1;
        const float* aq = sq + (h * 32 + mt * 16 + r) * QP + c4;
        uint32_t a[8][4];
#pragma unroll
        for (int kk = 0; kk < 8; kk++) {
            const int kb = kk * 8;
            a[kk][0] = __float_as_uint(aq[kb]);
            a[kk][1] = __float_as_uint(aq[8 * QP + kb]);
            a[kk][2] = __float_as_uint(aq[kb + 4]);
            a[kk][3] = __float_as_uint(aq[8 * QP + kb + 4]);
        }
#pragma unroll
        for (int nt = 0; nt < 2; nt++) {
            const int e0 = nh * 16 + nt * 8;
            const float* bk = sk + (h * 32 + e0 + r) * QP + c4;
            float c0 = 0.f, c1 = 0.f, c2 = 0.f, c3 = 0.f;
#pragma unroll
            for (int kk = 0; kk < 8; kk++) {
                const int kb = kk * 8;
                mma_tf32(c0, c1, c2, c3, a[kk][0], a[kk][1], a[kk][2], a[kk][3],
                         __float_as_uint(bk[kb]), __float_as_uint(bk[kb + 4]));
            }
            float* so = sat + (h * 32 + mt * 16 + r) * AP + e0 + 2 * c4;
            *(float2*)so            = make_float2(c0, c1);
            *(float2*)(so + 8 * AP) = make_float2(c2, c3);
        }
    }
    __syncthreads();

    // ---- P5: load v (tf32) into sk
    for (int i = tid; i < 512; i += 256) {
        const int ch = i >> 3, row = i & 7;
        const bf16* src = qkv + (size_t)(b * C3 + 128 + ch) * HW
                        + (size_t)(row0 + row) * Ww + col0;
        float f[8];
        bf8_to_f(*(const uint4*)src, f);
        float* dst = sk + ch * QP + row * 8;
        *(float4*)dst       = make_float4(tf32f(f[0]), tf32f(f[1]), tf32f(f[2]), tf32f(f[3]));
        *(float4*)(dst + 4) = make_float4(tf32f(f[4]), tf32f(f[5]), tf32f(f[6]), tf32f(f[7]));
    }
    // ---- P4: softmax (4 threads/row), write back tf32
    {
        const int rowi = tid >> 2, sub = tid & 3;
        float* rp = sat + rowi * AP + sub * 8;
        float4 v0 = *(const float4*)rp;
        float4 v1 = *(const float4*)(rp + 4);
        float m = fmaxf(fmaxf(fmaxf(v0.x, v0.y), fmaxf(v0.z, v0.w)),
                        fmaxf(fmaxf(v1.x, v1.y), fmaxf(v1.z, v1.w)));
        m = fmaxf(m, __shfl_xor_sync(0xffffffffu, m, 1));
        m = fmaxf(m, __shfl_xor_sync(0xffffffffu, m, 2));
        float e[8];
        e[0] = __expf(v0.x - m); e[1] = __expf(v0.y - m);
        e[2] = __expf(v0.z - m); e[3] = __expf(v0.w - m);
        e[4] = __expf(v1.x - m); e[5] = __expf(v1.y - m);
        e[6] = __expf(v1.z - m); e[7] = __expf(v1.w - m);
        float s = e[0]+e[1]+e[2]+e[3]+e[4]+e[5]+e[6]+e[7];
        s += __shfl_xor_sync(0xffffffffu, s, 1);
        s += __shfl_xor_sync(0xffffffffu, s, 2);
        const float inv = 1.f / s;
        *(float4*)rp       = make_float4(tf32f(e[0]*inv), tf32f(e[1]*inv),
                                         tf32f(e[2]*inv), tf32f(e[3]*inv));
        *(float4*)(rp + 4) = make_float4(tf32f(e[4]*inv), tf32f(e[5]*inv),
                                         tf32f(e[6]*inv), tf32f(e[7]*inv));
    }
    __syncthreads();

    // ---- P6: attn-out = softmax @ v  -> sq as [channel][pixel] tf32
    {
        const int h  = w >> 2, mt = (w >> 1) & 1, nq = w & 1;
        const float* aa = sat + (h * 32 + mt * 16 + r) * AP + c4;
        uint32_t a[4][4];
#pragma unroll
        for (int kk = 0; kk < 4; kk++) {
            const int kb = kk * 8;
            a[kk][0] = __float_as_uint(aa[kb]);
            a[kk][1] = __float_as_uint(aa[8 * AP + kb]);
            a[kk][2] = __float_as_uint(aa[kb + 4]);
            a[kk][3] = __float_as_uint(aa[8 * AP + kb + 4]);
        }
        float acc[4][4];
#pragma unroll
        for (int nt = 0; nt < 4; nt++)
#pragma unroll
            for (int j = 0; j < 4; j++) acc[nt][j] = 0.f;
#pragma unroll
        for (int nt = 0; nt < 4; nt++) {
            const int d0 = nq * 32 + nt * 8;
            const float* bv = sk + (h * 32 + c4) * QP + d0 + r;
#pragma unroll
            for (int kk = 0; kk < 4; kk++) {
                const int kb = kk * 8;
                mma_tf32(acc[nt][0], acc[nt][1], acc[nt][2], acc[nt][3],
                         a[kk][0], a[kk][1], a[kk][2], a[kk][3],
                         __float_as_uint(bv[kb * QP]),
                         __float_as_uint(bv[(kb + 4) * QP]));
            }
        }
        __syncthreads();
#pragma unroll
        for (int nt = 0; nt < 4; nt++) {
            const int d0 = nq * 32 + nt * 8;
            float* so = sq + (h * 32 + mt * 16 + r) * QP + d0 + 2 * c4;
            *(float2*)so            = make_float2(tf32f(acc[nt][0]), tf32f(acc[nt][1]));
            *(float2*)(so + 8 * QP) = make_float2(tf32f(acc[nt][2]), tf32f(acc[nt][3]));
        }
    }
    __syncthreads();

    // ---- P7: stage proj weights [o][k] tf32 into sk
    for (int idx = tid; idx < 64 * 64; idx += 256) {
        const int o = idx >> 6, k = idx & 63;
        sk[o * QP + k] = tf32f(pw[idx]);
    }
    __syncthreads();

    // ---- P8: proj MMA + bias + residual
    {
        const int mt = w >> 1, nh = w & 1;
        const float* aw = sk + (mt * 16 + r) * QP + c4;
        uint32_t a[8][4];
#pragma unroll
        for (int kk = 0; kk < 8; kk++) {
            const int kb = kk * 8;
            a[kk][0] = __float_as_uint(aw[kb]);
            a[kk][1] = __float_as_uint(aw[8 * QP + kb]);
            a[kk][2] = __float_as_uint(aw[kb + 4]);
            a[kk][3] = __float_as_uint(aw[8 * QP + kb + 4]);
        }
        const int o1 = mt * 16 + r, o2 = o1 + 8;
        const float bv1 = __ldg(&pb[o1]), bv2 = __ldg(&pb[o2]);
#pragma unroll
        for (int nt = 0; nt < 4; nt++) {
            const int p0 = nh * 32 + nt * 8;
            const float* bx = sq + c4 * QP + p0 + r;
            float c0 = 0.f, c1 = 0.f, c2 = 0.f, c3 = 0.f;
#pragma unroll
            for (int kk = 0; kk < 8; kk++) {
                const int kb = kk * 8;
                mma_tf32(c0, c1, c2, c3, a[kk][0], a[kk][1], a[kk][2], a[kk][3],
                         __float_as_uint(bx[kb * QP]),
                         __float_as_uint(bx[(kb + 4) * QP]));
            }
            const int p = p0 + 2 * c4;
            const size_t pixg = (size_t)(row0 + (p >> 3)) * Ww + col0 + (p & 7);
            {
                const size_t g = (size_t)(b * Cc + o1) * HW + pixg;
                float2 xr = *(const float2*)(xres + g);
                *(float2*)(xout + g) = make_float2(xr.x + c0 + bv1, xr.y + c1 + bv1);
            }
            {
                const size_t g = (size_t)(b * Cc + o2) * HW + pixg;
                float2 xr = *(const float2*)(xres + g);
                *(float2*)(xout + g) = make_float2(xr.x + c2 + bv2, xr.y + c3 + bv2);
            }
        }
    }
}

// ---------------- launcher ----------------------------------------------------
extern "C" void kernel_launch(void* const* d_in, const int* in_sizes, int n_in,
                              void* d_out, int out_size)
{
    const float* x     = (const float*)d_in[0];
    const float* ln1w  = (const float*)d_in[1];
    const float* ln1b  = (const float*)d_in[2];
    const float* qkvw  = (const float*)d_in[3];
    const float* qkvdw = (const float*)d_in[4];
    const float* temp  = (const float*)d_in[5];
    const float* projw = (const float*)d_in[6];
    const float* projb = (const float*)d_in[7];
    const float* ln2w  = (const float*)d_in[8];
    const float* ln2b  = (const float*)d_in[9];
    const float* pinw  = (const float*)d_in[10];
    const float* dww   = (const float*)d_in[11];
    const float* poutw = (const float*)d_in[12];
    float* out = (float*)d_out;

    bf16 *qkv, *qkv2, *mid, *y;
    float *x1, *wq, *wp, *wo;
    cudaGetSymbolAddress((void**)&qkv,  g_qkv);
    cudaGetSymbolAddress((void**)&qkv2, g_qkv2);
    cudaGetSymbolAddress((void**)&x1,   g_x1);
    cudaGetSymbolAddress((void**)&mid,  g_mid);
    cudaGetSymbolAddress((void**)&y,    g_y);
    cudaGetSymbolAddress((void**)&wq,   g_wq);
    cudaGetSymbolAddress((void**)&wp,   g_wp);
    cudaGetSymbolAddress((void**)&wo,   g_wo);

    k_prep<<<96, 256>>>(qkvw, pinw, poutw, wq, wp, wo);
    k_ln_mma2<C3, 192><<<(Bz * HW) / 128, 256>>>(x, ln1w, ln1b, wq, qkv);
    k_dw8<C3><<<(Bz * C3 * HW / 8) / 256, 256>>>(qkv, qkvdw, qkv2);
    k_attn_mma<<<Bz * 32 * 32, 256>>>(qkv2, temp, projw, projb, x, x1);
    k_ln_mma2<C2, 384><<<(Bz * HW) / 128, 256>>>(x1, ln2w, ln2b, wp, mid);
    k_dwgate8<<<(Bz * HID * HW / 8) / 256, 256>>>(mid, dww, y);
    k_pout2<<<(Bz * HW) / 64, 128>>>(y, wo, x1, out);
}

// round 6
// speedup vs baseline: 3.4614x; 1.1487x over previous
#include <cuda_runtime.h>
#include <cuda_bf16.h>
#include <math.h>
#include <stdint.h>

typedef __nv_bfloat16 bf16;

// Problem constants
#define Bz   4
#define Cc   64
#define Hh   256
#define Ww   256
#define HW   65536
#define HEADS 2
#define CH   32
#define WS   8
#define HID  170
#define C2   340
#define C3   192

// ---------------- scratch (device globals) ----------------
static __device__ bf16  g_qkv [(size_t)Bz*C3*HW];
static __device__ bf16  g_qkv2[(size_t)Bz*C3*HW];
static __device__ float g_x1  [(size_t)Bz*Cc*HW];       // residual carrier: fp32
static __device__ bf16  g_mid [(size_t)Bz*C2*HW];
static __device__ bf16  g_y   [(size_t)Bz*HID*HW];
// pre-transposed tf32 weights: [k][o]
static __device__ float g_wq  [64 * 192];
static __device__ float g_wp  [64 * 384];
static __device__ float g_wo  [192 * 64];

// ---------------- helpers ----------------
__device__ __forceinline__ uint32_t f2tf32(float x) {
    uint32_t u;
    asm("cvt.rna.tf32.f32 %0, %1;" : "=r"(u) : "f"(x));
    return u;
}
__device__ __forceinline__ float tf32f(float x) { return __uint_as_float(f2tf32(x)); }

__device__ __forceinline__ void mma_tf32(float& c0, float& c1, float& c2, float& c3,
                                         uint32_t a0, uint32_t a1, uint32_t a2, uint32_t a3,
                                         uint32_t b0, uint32_t b1)
{
    asm volatile("mma.sync.aligned.m16n8k8.row.col.f32.tf32.tf32.f32 "
        "{%0,%1,%2,%3}, {%4,%5,%6,%7}, {%8,%9}, {%0,%1,%2,%3};"
        : "+f"(c0), "+f"(c1), "+f"(c2), "+f"(c3)
        : "r"(a0), "r"(a1), "r"(a2), "r"(a3), "r"(b0), "r"(b1));
}

__device__ __forceinline__ void mma_bf16(float* c,
        uint32_t a0, uint32_t a1, uint32_t a2, uint32_t a3,
        uint32_t b0, uint32_t b1)
{
    asm volatile("mma.sync.aligned.m16n8k16.row.col.f32.bf16.bf16.f32 "
        "{%0,%1,%2,%3}, {%4,%5,%6,%7}, {%8,%9}, {%0,%1,%2,%3};"
        : "+f"(c[0]), "+f"(c[1]), "+f"(c[2]), "+f"(c[3])
        : "r"(a0), "r"(a1), "r"(a2), "r"(a3), "r"(b0), "r"(b1));
}

__device__ __forceinline__ void ldmx4t(uint32_t* a, uint32_t saddr) {
    asm volatile("ldmatrix.sync.aligned.m8n8.x4.trans.shared.b16 {%0,%1,%2,%3}, [%4];"
        : "=r"(a[0]), "=r"(a[1]), "=r"(a[2]), "=r"(a[3]) : "r"(saddr));
}

__device__ __forceinline__ uint32_t packbf(float x, float y) {
    __nv_bfloat162 t = __float22bfloat162_rn(make_float2(x, y));
    return *reinterpret_cast<uint32_t*>(&t);
}

// unpack 8 bf16 (uint4) -> 8 floats
__device__ __forceinline__ void bf8_to_f(const uint4& u, float* f) {
    float2 t;
    t = __bfloat1622float2(*reinterpret_cast<const __nv_bfloat162*>(&u.x)); f[0]=t.x; f[1]=t.y;
    t = __bfloat1622float2(*reinterpret_cast<const __nv_bfloat162*>(&u.y)); f[2]=t.x; f[3]=t.y;
    t = __bfloat1622float2(*reinterpret_cast<const __nv_bfloat162*>(&u.z)); f[4]=t.x; f[5]=t.y;
    t = __bfloat1622float2(*reinterpret_cast<const __nv_bfloat162*>(&u.w)); f[6]=t.x; f[7]=t.y;
}
__device__ __forceinline__ uint4 f_to_bf8(const float* f) {
    uint4 u;
    *reinterpret_cast<__nv_bfloat162*>(&u.x) = __float22bfloat162_rn(make_float2(f[0], f[1]));
    *reinterpret_cast<__nv_bfloat162*>(&u.y) = __float22bfloat162_rn(make_float2(f[2], f[3]));
    *reinterpret_cast<__nv_bfloat162*>(&u.z) = __float22bfloat162_rn(make_float2(f[4], f[5]));
    *reinterpret_cast<__nv_bfloat162*>(&u.w) = __float22bfloat162_rn(make_float2(f[6], f[7]));
    return u;
}

#define SXS 68
#define WSS 72
#define WSS32 40

// ---------------- K0: weight prep (transpose + tf32 convert) ------------------
__global__ void __launch_bounds__(256) k_prep(const float* __restrict__ qkvw,
        const float* __restrict__ pinw, const float* __restrict__ poutw,
        float* __restrict__ wq, float* __restrict__ wp, float* __restrict__ wo)
{
    const int t = blockIdx.x * 256 + threadIdx.x;
    if (t < 64 * 192) {
        const int k = t / 192, o = t % 192;
        wq[t] = tf32f(qkvw[o * 64 + k]);
    }
    if (t < 64 * 384) {
        const int k = t / 384, o = t % 384;
        wp[t] = (o < C2) ? tf32f(pinw[o * 64 + k]) : 0.f;
    }
    if (t < 192 * 64) {
        const int k = t / 64, o = t % 64;
        wo[t] = (k < HID) ? tf32f(poutw[o * HID + k]) : 0.f;
    }
}

// ---------------- K1/K4: fused LayerNorm + 1x1 conv, tf32 MMA, bf16 out -------
template<int COUT, int CPAD>
__global__ void __launch_bounds__(256) k_ln_mma2(const float* __restrict__ xin,
        const float* __restrict__ gw, const float* __restrict__ gb,
        const float* __restrict__ wT, bf16* __restrict__ out)
{
    __shared__ float sx[128 * SXS];
    __shared__ float ws[64 * WSS32];

    const int tid  = threadIdx.x;
    const int lane = tid & 31;
    const int warp = tid >> 5;
    const int p0   = blockIdx.x * 128;
    const int b    = p0 >> 16;
    const int hw0  = p0 & 65535;

    {
        const int pl = tid >> 1, half = tid & 1;
        const float* xp = xin + (size_t)(b * 64 + half * 32) * HW + hw0 + pl;
        float xv[32];
        float s = 0.f, s2 = 0.f;
#pragma unroll
        for (int i = 0; i < 32; i++) {
            xv[i] = xp[(size_t)i * HW];
            s += xv[i]; s2 += xv[i] * xv[i];
        }
        s  += __shfl_xor_sync(0xffffffffu, s, 1);
        s2 += __shfl_xor_sync(0xffffffffu, s2, 1);
        const float mu   = s * (1.f / 64.f);
        const float var  = fmaxf(s2 * (1.f / 64.f) - mu * mu, 0.f);
        const float rstd = rsqrtf(var + 1e-5f);
        float* sxp = sx + pl * SXS + half * 32;
#pragma unroll
        for (int i = 0; i < 32; i++) {
            const int c = half * 32 + i;
            sxp[i] = tf32f((xv[i] - mu) * rstd * __ldg(&gw[c]) + __ldg(&gb[c]));
        }
    }
    __syncthreads();

    const int r  = lane >> 2;
    const int c4 = lane & 3;
    const float* ap = sx + (warp * 16 + r) * SXS + c4;
    const float* bp = ws + c4 * WSS32 + r;

    uint32_t areg[8][4];
#pragma unroll
    for (int kk = 0; kk < 8; kk++) {
        const int kb = kk * 8;
        areg[kk][0] = __float_as_uint(ap[kb]);
        areg[kk][1] = __float_as_uint(ap[8 * SXS + kb]);
        areg[kk][2] = __float_as_uint(ap[kb + 4]);
        areg[kk][3] = __float_as_uint(ap[kb + 4 + 8 * SXS]);
    }

    const int pixb = hw0 + warp * 16 + r;
    const int NCH  = (COUT + 31) / 32;
    for (int chunk = 0; chunk < NCH; chunk++) {
        const int och = chunk * 32;
        __syncthreads();
        for (int idx = tid; idx < 64 * 32; idx += 256) {
            const int k = idx >> 5, o = idx & 31;
            ws[k * WSS32 + o] = wT[k * CPAD + och + o];
        }
        __syncthreads();

        float acc[4][4];
#pragma unroll
        for (int nt = 0; nt < 4; nt++)
#pragma unroll
            for (int j = 0; j < 4; j++) acc[nt][j] = 0.f;

#pragma unroll
        for (int kk = 0; kk < 8; kk++) {
            const int kb = kk * 8;
#pragma unroll
            for (int nt = 0; nt < 4; nt++) {
                const uint32_t b0 = __float_as_uint(bp[kb * WSS32 + nt * 8]);
                const uint32_t b1 = __float_as_uint(bp[(kb + 4) * WSS32 + nt * 8]);
                mma_tf32(acc[nt][0], acc[nt][1], acc[nt][2], acc[nt][3],
                         areg[kk][0], areg[kk][1], areg[kk][2], areg[kk][3], b0, b1);
            }
        }

#pragma unroll
        for (int nt = 0; nt < 4; nt++) {
            const int o = och + nt * 8 + 2 * c4;
            if ((COUT & 31) == 0 || o < COUT) {
                bf16* op = out + (size_t)(b * COUT + o) * HW + pixb;
                op[0]      = __float2bfloat16(acc[nt][0]);
                op[HW]     = __float2bfloat16(acc[nt][1]);
                op[8]      = __float2bfloat16(acc[nt][2]);
                op[HW + 8] = __float2bfloat16(acc[nt][3]);
            }
        }
    }
}

// ---------------- K6: pout (64 x 170) MMA + residual --------------------------
__global__ void __launch_bounds__(128) k_pout2(const bf16* __restrict__ y,
        const float* __restrict__ wT, const float* __restrict__ x1,
        float* __restrict__ out)
{
    __shared__ float sx[64 * SXS];
    __shared__ float ws[64 * WSS];

    const int tid  = threadIdx.x;
    const int lane = tid & 31;
    const int warp = tid >> 5;
    const int p0   = blockIdx.x * 64;
    const int b    = p0 >> 16;
    const int hw0  = p0 & 65535;

    const int r  = lane >> 2;
    const int c4 = lane & 3;
    const float* ap = sx + (warp * 16 + r) * SXS + c4;
    const float* bp = ws + c4 * WSS + r;

    float acc[8][4];
#pragma unroll
    for (int nt = 0; nt < 8; nt++)
#pragma unroll
        for (int j = 0; j < 4; j++) acc[nt][j] = 0.f;

    for (int kc = 0; kc < 192; kc += 64) {
        __syncthreads();
        {
            const int px = tid & 63, kh = tid >> 6;
            float* sxp = sx + px * SXS + kh * 32;
            const bf16* yp = y + (size_t)(b * HID + kc + kh * 32) * HW + hw0 + px;
#pragma unroll
            for (int j = 0; j < 32; j++) {
                const int gk = kc + kh * 32 + j;
                sxp[j] = (gk < HID) ? tf32f(__bfloat162float(yp[(size_t)j * HW])) : 0.f;
            }
        }
        for (int idx = tid; idx < 64 * 64; idx += 128) {
            const int k = idx >> 6, o = idx & 63;
            ws[k * WSS + o] = wT[(kc + k) * 64 + o];
        }
        __syncthreads();

#pragma unroll
        for (int kk = 0; kk < 8; kk++) {
            const int kb = kk * 8;
            const uint32_t a0 = __float_as_uint(ap[kb]);
            const uint32_t a1 = __float_as_uint(ap[8 * SXS + kb]);
            const uint32_t a2 = __float_as_uint(ap[kb + 4]);
            const uint32_t a3 = __float_as_uint(ap[kb + 4 + 8 * SXS]);
#pragma unroll
            for (int nt = 0; nt < 8; nt++) {
                const uint32_t b0 = __float_as_uint(bp[kb * WSS + nt * 8]);
                const uint32_t b1 = __float_as_uint(bp[(kb + 4) * WSS + nt * 8]);
                mma_tf32(acc[nt][0], acc[nt][1], acc[nt][2], acc[nt][3],
                         a0, a1, a2, a3, b0, b1);
            }
        }
    }

    const int pixb = hw0 + warp * 16 + r;
#pragma unroll
    for (int nt = 0; nt < 8; nt++) {
        const int o = nt * 8 + 2 * c4;
        const size_t g = (size_t)(b * 64 + o) * HW + pixb;
        out[g]          = x1[g]          + acc[nt][0];
        out[g + HW]     = x1[g + HW]     + acc[nt][1];
        out[g + 8]      = x1[g + 8]      + acc[nt][2];
        out[g + HW + 8] = x1[g + HW + 8] + acc[nt][3];
    }
}

// ---------------- K2/K5: depthwise 3x3, bf16, 8-wide ---------------------------
__device__ __forceinline__ void dw8(const bf16* __restrict__ ip, int h, int w0,
                                    const float* wk, float* acc)
{
#pragma unroll
    for (int kh = 0; kh < 3; kh++) {
        const int hh = h + kh - 1;
        if ((unsigned)hh >= 256u) continue;
        const bf16* rp = ip + hh * Ww + w0;
        float rv[10];
        rv[0] = (w0 > 0)   ? __bfloat162float(rp[-1]) : 0.f;
        rv[9] = (w0 < 248) ? __bfloat162float(rp[8])  : 0.f;
        uint4 u = *(const uint4*)rp;
        bf8_to_f(u, rv + 1);
        const float k0 = wk[kh * 3], k1 = wk[kh * 3 + 1], k2 = wk[kh * 3 + 2];
#pragma unroll
        for (int j = 0; j < 8; j++)
            acc[j] += k0 * rv[j] + k1 * rv[j + 1] + k2 * rv[j + 2];
    }
}

template<int CHAN>
__global__ void __launch_bounds__(256) k_dw8(const bf16* __restrict__ in,
        const float* __restrict__ wt, bf16* __restrict__ out)
{
    const int idx = blockIdx.x * 256 + threadIdx.x;
    const int hwo = idx & 8191;
    const int cb  = idx >> 13;
    const int ch  = cb % CHAN;
    const int h = hwo >> 5, w0 = (hwo & 31) * 8;
    float wk[9];
#pragma unroll
    for (int j = 0; j < 9; j++) wk[j] = __ldg(&wt[ch * 9 + j]);
    const bf16* ip = in + ((size_t)cb << 16);
    float acc[8] = {0,0,0,0,0,0,0,0};
    dw8(ip, h, w0, wk, acc);
    *(uint4*)(out + (size_t)idx * 8) = f_to_bf8(acc);
}

__global__ void __launch_bounds__(256) k_dwgate8(const bf16* __restrict__ in,
        const float* __restrict__ wt, bf16* __restrict__ out)
{
    const int idx = blockIdx.x * 256 + threadIdx.x;
    const int hwo = idx & 8191;
    const int cb  = idx >> 13;
    const int ch  = cb % HID;
    const int b   = cb / HID;
    const int h = hwo >> 5, w0 = (hwo & 31) * 8;

    float w1[9], w2[9];
#pragma unroll
    for (int j = 0; j < 9; j++) w1[j] = __ldg(&wt[ch * 9 + j]);
#pragma unroll
    for (int j = 0; j < 9; j++) w2[j] = __ldg(&wt[(ch + HID) * 9 + j]);

    const bf16* ip1 = in + (size_t)(b * C2 + ch) * HW;
    const bf16* ip2 = ip1 + (size_t)HID * HW;
    float a1[8] = {0,0,0,0,0,0,0,0}, a2[8] = {0,0,0,0,0,0,0,0};
    dw8(ip1, h, w0, w1, a1);
    dw8(ip2, h, w0, w2, a2);
    float o[8];
#pragma unroll
    for (int j = 0; j < 8; j++) {
        const float ge = 0.5f * a1[j] * (1.0f + erff(a1[j] * 0.70710678118654752f));
        o[j] = ge * a2[j];
    }
    *(uint4*)(out + (size_t)idx * 8) = f_to_bf8(o);
}

// ---------------- K3: window attention, bf16 MMA, 2 windows/block -------------
// smem word-stride 36 (=4 mod 32 -> conflict-free frags). 3 buffers of 18KB.
#define ATT_SMEM 55296
__global__ void __launch_bounds__(256, 4) k_attn_bf16(const bf16* __restrict__ qkv,
        const float* __restrict__ temp, const float* __restrict__ pw,
        const float* __restrict__ pb, const float* __restrict__ xres,
        float* __restrict__ xout)
{
    extern __shared__ char smem[];
    uint32_t* sq = (uint32_t*)smem;              // q bf16 [2win*64][36w] -> attnout_T
    uint32_t* sk = (uint32_t*)(smem + 18432);    // k bf16 -> proj weights [64][36w]
    uint32_t* sv = (uint32_t*)(smem + 36864);    // v bf16 [2win*64 ch][36w]

    const int tid  = threadIdx.x;
    const int lane = tid & 31;
    const int w    = tid >> 5;
    const int r    = lane >> 2;
    const int c4   = lane & 3;

    const int blk  = blockIdx.x;
    const int b    = blk >> 9;
    const int row0 = ((blk >> 4) & 31) * 8;
    const int col0 = (blk & 15) * 16;

    // ---- P1: gather q,k,v (raw bf16 uint4 strips; 2 windows -> 32B lines)
    for (int i = tid; i < 2048; i += 256) {
        const int hv = i & 1, row = (i >> 1) & 7, ch = (i >> 4) & 63, s = i >> 10;
        const bf16* src = qkv + ((size_t)(b * C3 + s * 64 + ch) << 16)
                        + (row0 + row) * Ww + col0 + hv * 8;
        uint4 u = *(const uint4*)src;
        uint32_t* dst = ((s == 0) ? sq : sk) + (hv * 64 + ch) * 36 + row * 4;
        *(uint4*)dst = u;
    }
    for (int i = tid; i < 1024; i += 256) {
        const int hv = i & 1, row = (i >> 1) & 7, ch = (i >> 4) & 63;
        const bf16* src = qkv + ((size_t)(b * C3 + 128 + ch) << 16)
                        + (row0 + row) * Ww + col0 + hv * 8;
        uint4 u = *(const uint4*)src;
        *(uint4*)(sv + (hv * 64 + ch) * 36 + row * 4) = u;
    }
    __syncthreads();

    // ---- P2: l2-normalize q,k rows in place (q also * temperature)
#pragma unroll
    for (int it = 0; it < 2; it++) {
        const int idx = tid + it * 256;          // 0..511
        const int rown = idx >> 1, hw2 = idx & 1;
        uint32_t* base = ((rown < 128) ? sq : sk) + (rown & 127) * 36 + hw2 * 16;
        float v[32]; float ss = 0.f;
#pragma unroll
        for (int j = 0; j < 4; j++) {
            uint4 u = *(uint4*)(base + j * 4);
            bf8_to_f(u, v + j * 8);
        }
#pragma unroll
        for (int j = 0; j < 32; j++) ss += v[j] * v[j];
        ss += __shfl_xor_sync(0xffffffffu, ss, 1);
        float sc = 1.f / fmaxf(sqrtf(ss), 1e-12f);
        if (rown < 128) sc *= __ldg(&temp[(rown >> 5) & 1]);
#pragma unroll
        for (int j = 0; j < 4; j++) {
            float t2[8];
#pragma unroll
            for (int m = 0; m < 8; m++) t2[m] = v[j * 8 + m] * sc;
            *(uint4*)(base + j * 4) = f_to_bf8(t2);
        }
    }
    __syncthreads();

    // warp roles: win = w>>2, h = (w>>1)&1, mh = w&1
    const int win = w >> 2, h = (w >> 1) & 1, mh = w & 1;

    // ---- GEMM1: logits[c 16][e 32] = q @ k^T (K=64 d), acc in regs
    float acc1[4][4];
#pragma unroll
    for (int nt = 0; nt < 4; nt++)
#pragma unroll
        for (int j = 0; j < 4; j++) acc1[nt][j] = 0.f;
    {
        const uint32_t* qb = sq + (win * 64 + h * 32 + mh * 16) * 36;
        const uint32_t* kb = sk + (win * 64 + h * 32) * 36;
#pragma unroll
        for (int kk = 0; kk < 4; kk++) {
            const int ko = kk * 8 + c4;
            const uint32_t a0 = qb[r * 36 + ko];
            const uint32_t a1 = qb[(r + 8) * 36 + ko];
            const uint32_t a2 = qb[r * 36 + ko + 4];
            const uint32_t a3 = qb[(r + 8) * 36 + ko + 4];
#pragma unroll
            for (int nt = 0; nt < 4; nt++) {
                const uint32_t b0 = kb[(nt * 8 + r) * 36 + ko];
                const uint32_t b1 = kb[(nt * 8 + r) * 36 + ko + 4];
                mma_bf16(acc1[nt], a0, a1, a2, a3, b0, b1);
            }
        }
    }

    // ---- softmax in registers (rows r and r+8; 4 lanes per row via shfl)
    uint32_t battn[2][4];
    {
        float m1 = -1e30f, m2 = -1e30f;
#pragma unroll
        for (int nt = 0; nt < 4; nt++) {
            m1 = fmaxf(m1, fmaxf(acc1[nt][0], acc1[nt][1]));
            m2 = fmaxf(m2, fmaxf(acc1[nt][2], acc1[nt][3]));
        }
        m1 = fmaxf(m1, __shfl_xor_sync(0xffffffffu, m1, 1));
        m1 = fmaxf(m1, __shfl_xor_sync(0xffffffffu, m1, 2));
        m2 = fmaxf(m2, __shfl_xor_sync(0xffffffffu, m2, 1));
        m2 = fmaxf(m2, __shfl_xor_sync(0xffffffffu, m2, 2));
        float s1 = 0.f, s2 = 0.f;
#pragma unroll
        for (int nt = 0; nt < 4; nt++) {
            acc1[nt][0] = __expf(acc1[nt][0] - m1);
            acc1[nt][1] = __expf(acc1[nt][1] - m1);
            acc1[nt][2] = __expf(acc1[nt][2] - m2);
            acc1[nt][3] = __expf(acc1[nt][3] - m2);
            s1 += acc1[nt][0] + acc1[nt][1];
            s2 += acc1[nt][2] + acc1[nt][3];
        }
        s1 += __shfl_xor_sync(0xffffffffu, s1, 1);
        s1 += __shfl_xor_sync(0xffffffffu, s1, 2);
        s2 += __shfl_xor_sync(0xffffffffu, s2, 1);
        s2 += __shfl_xor_sync(0xffffffffu, s2, 2);
        const float i1 = 1.f / s1, i2 = 1.f / s2;
#pragma unroll
        for (int kk2 = 0; kk2 < 2; kk2++) {
            battn[kk2][0] = packbf(acc1[2*kk2][0] * i1,   acc1[2*kk2][1] * i1);
            battn[kk2][1] = packbf(acc1[2*kk2+1][0] * i1, acc1[2*kk2+1][1] * i1);
            battn[kk2][2] = packbf(acc1[2*kk2][2] * i2,   acc1[2*kk2][3] * i2);
            battn[kk2][3] = packbf(acc1[2*kk2+1][2] * i2, acc1[2*kk2+1][3] * i2);
        }
    }
    __syncthreads();   // all q/k reads done; sq/sk reusable

    // ---- GEMM2 (transposed): attnout^T[d 64][c 16] = V^T @ attn^T
    // A = V^T via ldmatrix.trans from natural [e][d] layout; B = battn regs.
    {
        const uint32_t svb = (uint32_t)__cvta_generic_to_shared(sv)
                           + (uint32_t)((win * 64 + h * 32) * 144);
        const int erow = ((lane >> 4) & 1) * 8 + (lane & 7);
        const int dcol = ((lane >> 3) & 1) * 8;
#pragma unroll
        for (int mt = 0; mt < 4; mt++) {
            float a2c[2][4];
#pragma unroll
            for (int nt = 0; nt < 2; nt++)
#pragma unroll
                for (int j = 0; j < 4; j++) a2c[nt][j] = 0.f;
#pragma unroll
            for (int kk2 = 0; kk2 < 2; kk2++) {
                uint32_t av[4];
                ldmx4t(av, svb + (uint32_t)((kk2 * 16 + erow) * 144
                                            + (mt * 16 + dcol) * 2));
                mma_bf16(a2c[0], av[0], av[1], av[2], av[3], battn[kk2][0], battn[kk2][1]);
                mma_bf16(a2c[1], av[0], av[1], av[2], av[3], battn[kk2][2], battn[kk2][3]);
            }
            // store attnout^T bf16 into sq: word (win*64+d)*36 + c/2
            const int base0 = (win * 64 + mt * 16 + r) * 36 + h * 16 + mh * 8 + c4;
            sq[base0]          = packbf(a2c[0][0], a2c[0][1]);
            sq[base0 + 4]      = packbf(a2c[1][0], a2c[1][1]);
            sq[base0 + 8 * 36]     = packbf(a2c[0][2], a2c[0][3]);
            sq[base0 + 8 * 36 + 4] = packbf(a2c[1][2], a2c[1][3]);
        }
    }

    // ---- stage proj weights bf16 [o][c] into sk
    for (int idx = tid; idx < 2048; idx += 256) {
        const int o = idx >> 5, cw = idx & 31;
        sk[o * 36 + cw] = packbf(pw[o * 64 + cw * 2], pw[o * 64 + cw * 2 + 1]);
    }
    __syncthreads();

    // ---- GEMM3: proj + bias + residual. warp = (win, oq)
    {
        const int oq = w & 3;                    // win = w>>2 (same as above)
        const uint32_t* wpb = sk + (oq * 16) * 36;
        const uint32_t* ab  = sq + (win * 64) * 36;
        uint32_t a3r[4][4];
#pragma unroll
        for (int kk = 0; kk < 4; kk++) {
            const int ko = kk * 8 + c4;
            a3r[kk][0] = wpb[r * 36 + ko];
            a3r[kk][1] = wpb[(r + 8) * 36 + ko];
            a3r[kk][2] = wpb[r * 36 + ko + 4];
            a3r[kk][3] = wpb[(r + 8) * 36 + ko + 4];
        }
        const int o1 = oq * 16 + r, o2 = o1 + 8;
        const float bv1 = __ldg(&pb[o1]), bv2 = __ldg(&pb[o2]);
        const int pcol = col0 + win * 8 + 2 * c4;
#pragma unroll
        for (int nt = 0; nt < 8; nt++) {
            float c[4] = {0.f, 0.f, 0.f, 0.f};
#pragma unroll
            for (int kk = 0; kk < 4; kk++) {
                const int ko = kk * 8 + c4;
                const uint32_t b0 = ab[(nt * 8 + r) * 36 + ko];
                const uint32_t b1 = ab[(nt * 8 + r) * 36 + ko + 4];
                mma_bf16(c, a3r[kk][0], a3r[kk][1], a3r[kk][2], a3r[kk][3], b0, b1);
            }
            const size_t g1 = ((size_t)(b * Cc + o1) << 16) + (row0 + nt) * Ww + pcol;
            const size_t g2 = ((size_t)(b * Cc + o2) << 16) + (row0 + nt) * Ww + pcol;
            float2 x1v = *(const float2*)(xres + g1);
            float2 x2v = *(const float2*)(xres + g2);
            *(float2*)(xout + g1) = make_float2(x1v.x + c[0] + bv1, x1v.y + c[1] + bv1);
            *(float2*)(xout + g2) = make_float2(x2v.x + c[2] + bv2, x2v.y + c[3] + bv2);
        }
    }
}

// ---------------- launcher ----------------------------------------------------
extern "C" void kernel_launch(void* const* d_in, const int* in_sizes, int n_in,
                              void* d_out, int out_size)
{
    const float* x     = (const float*)d_in[0];
    const float* ln1w  = (const float*)d_in[1];
    const float* ln1b  = (const float*)d_in[2];
    const float* qkvw  = (const float*)d_in[3];
    const float* qkvdw = (const float*)d_in[4];
    const float* temp  = (const float*)d_in[5];
    const float* projw = (const float*)d_in[6];
    const float* projb = (const float*)d_in[7];
    const float* ln2w  = (const float*)d_in[8];
    const float* ln2b  = (const float*)d_in[9];
    const float* pinw  = (const float*)d_in[10];
    const float* dww   = (const float*)d_in[11];
    const float* poutw = (const float*)d_in[12];
    float* out = (float*)d_out;

    bf16 *qkv, *qkv2, *mid, *y;
    float *x1, *wq, *wp, *wo;
    cudaGetSymbolAddress((void**)&qkv,  g_qkv);
    cudaGetSymbolAddress((void**)&qkv2, g_qkv2);
    cudaGetSymbolAddress((void**)&x1,   g_x1);
    cudaGetSymbolAddress((void**)&mid,  g_mid);
    cudaGetSymbolAddress((void**)&y,    g_y);
    cudaGetSymbolAddress((void**)&wq,   g_wq);
    cudaGetSymbolAddress((void**)&wp,   g_wp);
    cudaGetSymbolAddress((void**)&wo,   g_wo);

    cudaFuncSetAttribute(k_attn_bf16,
        cudaFuncAttributeMaxDynamicSharedMemorySize, ATT_SMEM);

    k_prep<<<96, 256>>>(qkvw, pinw, poutw, wq, wp, wo);
    k_ln_mma2<C3, 192><<<(Bz * HW) / 128, 256>>>(x, ln1w, ln1b, wq, qkv);
    k_dw8<C3><<<(Bz * C3 * HW / 8) / 256, 256>>>(qkv, qkvdw, qkv2);
    k_attn_bf16<<<Bz * 32 * 16, 256, ATT_SMEM>>>(qkv2, temp, projw, projb, x, x1);
    k_ln_mma2<C2, 384><<<(Bz * HW) / 128, 256>>>(x1, ln2w, ln2b, wp, mid);
    k_dwgate8<<<(Bz * HID * HW / 8) / 256, 256>>>(mid, dww, y);
    k_pout2<<<(Bz * HW) / 64, 128>>>(y, wo, x1, out);
}